// round 10
// baseline (speedup 1.0000x reference)
#include <cuda_runtime.h>
#include <cuda_fp16.h>
#include <math.h>

#define NNODES 50000
#define NEDGES 800000
#define NETOT  (NEDGES + NNODES)
#define NGRAPH 64
#define NBLK_SCAN ((NNODES + 255) / 256)   // 196
#define HEADS_BLOCKS 592
#define NODES_A 25088                      // 196 gemm row-blocks
#define YBLK_A 196
#define YBLK_B 195                         // covers rows 25088..50000
#define YBLK_FULL 391

// ---------------- scratch (device globals; no allocation allowed) ----------------
__device__ __half g_hh0[NNODES * 256];   // projected features fp16, buffer 0 (layers 1,3)
__device__ __half g_hh1[NNODES * 256];   // buffer 1 (layer 2)
__device__ __half g_xh1[NNODES * 128];   // layer-1 input, fp16
__device__ __half g_xh[NNODES * 64];     // layer-2/3 input, fp16
__device__ float g_als[NNODES * 4];      // src attention logit per head
__device__ float g_ald[NNODES * 4];      // dst attention logit per head
__device__ int   g_deg[NNODES];
__device__ int   g_rowptr[NNODES + 1];
__device__ int   g_cursor[NNODES];
__device__ int   g_bsum[256];
__device__ uint4 g_erec[NETOT];          // AoS: {src, dst, ew01(h2), ew23(h2)}

// ---------------- helpers ----------------
__device__ __forceinline__ float warp_sum(float v) {
  #pragma unroll
  for (int o = 16; o; o >>= 1) v += __shfl_xor_sync(0xffffffffu, v, o);
  return v;
}
__device__ __forceinline__ float lrelu(float v) { return v > 0.f ? v : 0.2f * v; }

typedef unsigned long long ull;
__device__ __forceinline__ ull pack2(float x, float y) {
  ull r; asm("mov.b64 %0,{%1,%2};" : "=l"(r) : "f"(x), "f"(y)); return r;
}
__device__ __forceinline__ void ffma2(ull& d, ull a, ull b) {
  asm("fma.rn.f32x2 %0,%1,%2,%0;" : "+l"(d) : "l"(a), "l"(b));
}
__device__ __forceinline__ void fadd2(ull& d, ull a) {
  asm("add.rn.f32x2 %0,%0,%1;" : "+l"(d) : "l"(a));
}
__device__ __forceinline__ float2 unpack2(ull v) {
  float2 f; asm("mov.b64 {%0,%1},%2;" : "=f"(f.x), "=f"(f.y) : "l"(v)); return f;
}

// ---------------- CSR build ----------------
__global__ void k_count(const int* __restrict__ ei) {
  int i = blockIdx.x * blockDim.x + threadIdx.x;
  if (i >= NETOT) return;
  int d = (i < NEDGES) ? ei[NEDGES + i] : (i - NEDGES);   // self-loops appended
  atomicAdd(&g_deg[d], 1);
}

__global__ void k_scan1() {
  __shared__ int tmp[256];
  int tid = threadIdx.x;
  int i = blockIdx.x * 256 + tid;
  int v = (i < NNODES) ? g_deg[i] : 0;
  tmp[tid] = v;
  __syncthreads();
  #pragma unroll
  for (int d = 1; d < 256; d <<= 1) {
    int t = (tid >= d) ? tmp[tid - d] : 0;
    __syncthreads();
    tmp[tid] += t;
    __syncthreads();
  }
  if (i < NNODES) g_rowptr[i] = tmp[tid] - v;   // exclusive within block
  if (tid == 255) g_bsum[blockIdx.x] = tmp[255];
}

// fused: per-block offset = sum of bsum[0..bid-1], computed redundantly per block
__global__ void k_scan23() {
  __shared__ int red[256];
  int tid = threadIdx.x;
  int bid = blockIdx.x;
  int v = (tid < bid && tid < NBLK_SCAN) ? g_bsum[tid] : 0;
  red[tid] = v;
  __syncthreads();
  #pragma unroll
  for (int o = 128; o; o >>= 1) {
    if (tid < o) red[tid] += red[tid + o];
    __syncthreads();
  }
  int off = red[0];
  int i = bid * 256 + tid;
  if (i < NNODES) {
    int r = g_rowptr[i] + off;
    g_rowptr[i] = r;
    g_cursor[i] = r;
  }
  if (i == 0) g_rowptr[NNODES] = NETOT;
}

// fill CSR record AND layer-1 edge weights in one ST.128 (gemm1 logits ready)
__global__ void k_fill_ew1(const int* __restrict__ ei) {
  int i = blockIdx.x * blockDim.x + threadIdx.x;
  if (i >= NETOT) return;
  int s, d;
  if (i < NEDGES) { s = ei[i]; d = ei[NEDGES + i]; }
  else            { s = i - NEDGES; d = s; }
  int pos = atomicAdd(&g_cursor[d], 1);
  float4 as = ((const float4*)g_als)[s];
  float4 ad = ((const float4*)g_ald)[d];
  __half2 e01 = __floats2half2_rn(__expf(lrelu(as.x + ad.x)), __expf(lrelu(as.y + ad.y)));
  __half2 e23 = __floats2half2_rn(__expf(lrelu(as.z + ad.z)), __expf(lrelu(as.w + ad.w)));
  uint4 rec;
  rec.x = (unsigned)s;
  rec.y = (unsigned)d;
  rec.z = *reinterpret_cast<unsigned*>(&e01);
  rec.w = *reinterpret_cast<unsigned*>(&e23);
  g_erec[pos] = rec;
}

// ---------------- layer-1 input cast fp32 -> fp16 ----------------
__global__ void k_xcast(const float* __restrict__ x) {
  int i = blockIdx.x * blockDim.x + threadIdx.x;   // float4 index
  if (i >= NNODES * 32) return;
  float4 v = ((const float4*)x)[i];
  __half2* o = (__half2*)g_xh1;
  o[i * 2]     = __floats2half2_rn(v.x, v.y);
  o[i * 2 + 1] = __floats2half2_rn(v.z, v.w);
}

// ---------------- edge-parallel softmax weights (layers 2, 3) ----------------
__global__ void k_edgew() {
  int e = blockIdx.x * blockDim.x + threadIdx.x;
  if (e >= NETOT) return;
  int2 sd = *reinterpret_cast<const int2*>(&g_erec[e]);
  float4 as = ((const float4*)g_als)[sd.x];
  float4 ad = ((const float4*)g_ald)[sd.y];
  __half2 e01 = __floats2half2_rn(__expf(lrelu(as.x + ad.x)), __expf(lrelu(as.y + ad.y)));
  __half2 e23 = __floats2half2_rn(__expf(lrelu(as.z + ad.z)), __expf(lrelu(as.w + ad.w)));
  uint2 wv;
  wv.x = *reinterpret_cast<unsigned*>(&e01);
  wv.y = *reinterpret_cast<unsigned*>(&e23);
  *reinterpret_cast<uint2*>(reinterpret_cast<char*>(&g_erec[e]) + 8) = wv;
}

// ---------------- tensor-core GEMM + logit epilogue ----------------
__device__ __forceinline__ void ldsm4(unsigned& r0, unsigned& r1, unsigned& r2, unsigned& r3,
                                      unsigned addr) {
  asm volatile("ldmatrix.sync.aligned.m8n8.x4.shared.b16 {%0,%1,%2,%3}, [%4];"
               : "=r"(r0), "=r"(r1), "=r"(r2), "=r"(r3) : "r"(addr));
}
__device__ __forceinline__ void ldsm2t(unsigned& r0, unsigned& r1, unsigned addr) {
  asm volatile("ldmatrix.sync.aligned.m8n8.x2.trans.shared.b16 {%0,%1}, [%2];"
               : "=r"(r0), "=r"(r1) : "r"(addr));
}
__device__ __forceinline__ void mma16816(float* c, const unsigned* a, const unsigned* b) {
  asm volatile("mma.sync.aligned.m16n8k16.row.col.f32.f16.f16.f32 "
               "{%0,%1,%2,%3},{%4,%5,%6,%7},{%8,%9},{%0,%1,%2,%3};"
               : "+f"(c[0]), "+f"(c[1]), "+f"(c[2]), "+f"(c[3])
               : "r"(a[0]), "r"(a[1]), "r"(a[2]), "r"(a[3]), "r"(b[0]), "r"(b[1]));
}

template<int K>
__global__ void __launch_bounds__(256) k_gemm_mma(
    int src_sel, const float* __restrict__ W,
    const float* __restrict__ a_s, const float* __restrict__ a_d,
    int yoff, int hh_sel) {
  constexpr int APAD = K + 8;
  constexpr int A_BYTES = 128 * APAD * 2;
  constexpr int B_BYTES = K * 72 * 2;
  extern __shared__ __align__(16) char dyn[];
  __half* As = (__half*)dyn;
  __half* Bs = (__half*)(dyn + A_BYTES);
  float* s_as = (float*)(dyn + A_BYTES + B_BYTES);
  float* s_ad = s_as + 64;
  float* red_s = (float*)dyn;                // overlay after mma: [128][2]
  float* red_d = (float*)(dyn + 1024);

  const __half* __restrict__ X = (src_sel == 0) ? g_xh1 : g_xh;
  __half* __restrict__ HH = hh_sel ? g_hh1 : g_hh0;
  int tid = threadIdx.x;
  int lane = tid & 31, wid = tid >> 5;
  int warp_m = wid >> 1, warp_n = wid & 1;
  int hd = blockIdx.x;
  int col0 = hd * 64;
  int row0 = (blockIdx.y + yoff) * 128;

  if (tid < 64) { s_as[tid] = a_s[col0 + tid]; s_ad[tid] = a_d[col0 + tid]; }

  constexpr int A_IT = 128 * K / 8 / 256;
  #pragma unroll
  for (int it = 0; it < A_IT; it++) {
    int idx = tid + it * 256;
    int r = idx / (K / 8), c8 = idx % (K / 8);
    uint4 v = make_uint4(0, 0, 0, 0);
    if (row0 + r < NNODES)
      v = *(const uint4*)&X[(size_t)(row0 + r) * K + c8 * 8];
    *(uint4*)&As[r * APAD + c8 * 8] = v;
  }
  constexpr int B_IT = K * 16 / 256;
  #pragma unroll
  for (int it = 0; it < B_IT; it++) {
    int idx = tid + it * 256;
    int k = idx >> 4, c4 = idx & 15;
    float4 v = *(const float4*)&W[(size_t)k * 256 + col0 + c4 * 4];
    __half2* o = (__half2*)&Bs[k * 72 + c4 * 4];
    o[0] = __floats2half2_rn(v.x, v.y);
    o[1] = __floats2half2_rn(v.z, v.w);
  }
  __syncthreads();

  unsigned As_u = (unsigned)__cvta_generic_to_shared(As);
  unsigned Bs_u = (unsigned)__cvta_generic_to_shared(Bs);
  unsigned a_base = As_u + ((warp_m * 32 + (lane & 15)) * APAD + (lane >> 4) * 8) * 2;
  unsigned b_base = Bs_u + ((lane & 15) * 72 + warp_n * 32) * 2;

  float acc[2][4][4];
  #pragma unroll
  for (int mt = 0; mt < 2; mt++)
    #pragma unroll
    for (int nt = 0; nt < 4; nt++)
      #pragma unroll
      for (int q = 0; q < 4; q++) acc[mt][nt][q] = 0.f;

  #pragma unroll
  for (int ks = 0; ks < K / 16; ks++) {
    unsigned a[2][4], b[4][2];
    #pragma unroll
    for (int mt = 0; mt < 2; mt++)
      ldsm4(a[mt][0], a[mt][1], a[mt][2], a[mt][3],
            a_base + (mt * 16 * APAD + ks * 16) * 2);
    #pragma unroll
    for (int nt = 0; nt < 4; nt++)
      ldsm2t(b[nt][0], b[nt][1], b_base + (ks * 16 * 72 + nt * 8) * 2);
    #pragma unroll
    for (int mt = 0; mt < 2; mt++)
      #pragma unroll
      for (int nt = 0; nt < 4; nt++)
        mma16816(acc[mt][nt], a[mt], b[nt]);
  }
  __syncthreads();   // reds overlay As

  int quad = lane >> 2, qid = lane & 3;
  #pragma unroll
  for (int mt = 0; mt < 2; mt++) {
    #pragma unroll
    for (int rh = 0; rh < 2; rh++) {
      int lr = warp_m * 32 + mt * 16 + rh * 8 + quad;
      int row = row0 + lr;
      float ss = 0.f, sd = 0.f;
      #pragma unroll
      for (int nt = 0; nt < 4; nt++) {
        float v0 = acc[mt][nt][rh * 2 + 0];
        float v1 = acc[mt][nt][rh * 2 + 1];
        int c = warp_n * 32 + nt * 8 + qid * 2;     // local even channel
        ss = fmaf(v0, s_as[c], fmaf(v1, s_as[c + 1], ss));
        sd = fmaf(v0, s_ad[c], fmaf(v1, s_ad[c + 1], sd));
        if (row < NNODES)   // lane-interleaved layout: 8*(c/2) + 2*hd
          *(__half2*)&HH[(size_t)row * 256 + c * 4 + hd * 2] = __floats2half2_rn(v0, v1);
      }
      ss += __shfl_xor_sync(0xffffffffu, ss, 1);
      ss += __shfl_xor_sync(0xffffffffu, ss, 2);
      sd += __shfl_xor_sync(0xffffffffu, sd, 1);
      sd += __shfl_xor_sync(0xffffffffu, sd, 2);
      if (qid == 0) { red_s[lr * 2 + warp_n] = ss; red_d[lr * 2 + warp_n] = sd; }
    }
  }
  __syncthreads();
  if (tid < 128) {
    int row = row0 + tid;
    if (row < NNODES) {
      g_als[row * 4 + hd] = red_s[tid * 2] + red_s[tid * 2 + 1];
      g_ald[row * 4 + hd] = red_d[tid * 2] + red_d[tid * 2 + 1];
    }
  }
}

// ---------------- GAT aggregate (one warp per node, node range [n0,n1)) ----------------
// lane l owns channels {2l, 2l+1} of all 4 heads: one LDG.128 feature gather +
// one LDG.128 AoS metadata record per edge.
__global__ void k_aggregate(const float* __restrict__ bias, float* __restrict__ xout,
                            int fp16_relu, int n0, int n1, int hh_sel) {
  int w = n0 + ((blockIdx.x * blockDim.x + threadIdx.x) >> 5);
  int lane = threadIdx.x & 31;
  if (w >= n1) return;
  int beg = g_rowptr[w], end = g_rowptr[w + 1];
  const uint4* __restrict__ H4 = (const uint4*)(hh_sel ? g_hh1 : g_hh0);
  const uint4* __restrict__ REC = (const uint4*)g_erec;

  ull acc0 = 0, acc1 = 0, acc2 = 0, acc3 = 0;
  ull dd01 = 0, dd23 = 0;

#define EDGE_ACC(hv, rec)                                                 \
  do {                                                                    \
    float2 w01 = __half22float2(*reinterpret_cast<const __half2*>(&(rec).z)); \
    float2 w23 = __half22float2(*reinterpret_cast<const __half2*>(&(rec).w)); \
    fadd2(dd01, pack2(w01.x, w01.y));                                     \
    fadd2(dd23, pack2(w23.x, w23.y));                                     \
    float2 f0 = __half22float2(*(__half2*)&(hv).x);                       \
    float2 f1 = __half22float2(*(__half2*)&(hv).y);                       \
    float2 f2 = __half22float2(*(__half2*)&(hv).z);                       \
    float2 f3 = __half22float2(*(__half2*)&(hv).w);                       \
    ffma2(acc0, pack2(f0.x, f0.y), pack2(w01.x, w01.x));                  \
    ffma2(acc1, pack2(f1.x, f1.y), pack2(w01.y, w01.y));                  \
    ffma2(acc2, pack2(f2.x, f2.y), pack2(w23.x, w23.x));                  \
    ffma2(acc3, pack2(f3.x, f3.y), pack2(w23.y, w23.y));                  \
  } while (0)

  int e = beg;
  for (; e + 4 <= end; e += 4) {
    uint4 r0 = REC[e], r1 = REC[e + 1], r2 = REC[e + 2], r3 = REC[e + 3];
    uint4 h0 = H4[(size_t)r0.x * 32 + lane];
    uint4 h1 = H4[(size_t)r1.x * 32 + lane];
    uint4 h2 = H4[(size_t)r2.x * 32 + lane];
    uint4 h3 = H4[(size_t)r3.x * 32 + lane];
    EDGE_ACC(h0, r0);
    EDGE_ACC(h1, r1);
    EDGE_ACC(h2, r2);
    EDGE_ACC(h3, r3);
  }
  for (; e < end; e++) {
    uint4 rv = REC[e];
    uint4 hv = H4[(size_t)rv.x * 32 + lane];
    EDGE_ACC(hv, rv);
  }
#undef EDGE_ACC

  float2 d01 = unpack2(dd01), d23 = unpack2(dd23);
  float2 a0 = unpack2(acc0), a1 = unpack2(acc1), a2 = unpack2(acc2), a3 = unpack2(acc3);
  float r0 = 1.f / d01.x, r1 = 1.f / d01.y, r2 = 1.f / d23.x, r3 = 1.f / d23.y;
  float2 bv = ((const float2*)bias)[lane];
  float2 o;
  o.x = (a0.x * r0 + a1.x * r1 + a2.x * r2 + a3.x * r3) * 0.25f + bv.x;
  o.y = (a0.y * r0 + a1.y * r1 + a2.y * r2 + a3.y * r3) * 0.25f + bv.y;
  if (fp16_relu) {
    o.x = fmaxf(o.x, 0.f); o.y = fmaxf(o.y, 0.f);
    ((__half2*)g_xh)[(size_t)w * 32 + lane] = __floats2half2_rn(o.x, o.y);
  } else {
    ((float2*)xout)[(size_t)w * 32 + lane] = o;
  }
}

// ---------------- per-node MLP heads (grid-stride; weights loaded once per block) ----------------
__global__ void __launch_bounds__(256) k_heads(
                        const float* __restrict__ emb,
                        const float* __restrict__ aw1, const float* __restrict__ ab1,
                        const float* __restrict__ aw2, const float* __restrict__ ab2,
                        const float* __restrict__ rw1, const float* __restrict__ rb1,
                        const float* __restrict__ rw2, const float* __restrict__ rb2,
                        const float* __restrict__ cw1, const float* __restrict__ cb1,
                        const float* __restrict__ cw2, const float* __restrict__ cb2,
                        float* __restrict__ anomaly, float* __restrict__ risk,
                        float* __restrict__ resource) {
  __shared__ float s_a1[2048], s_r1[2048], s_c1[2048];
  __shared__ float s_a2[32], s_r2[32], s_c2[160];
  __shared__ float s_ab1[32], s_rb1[32], s_cb1[32];
  __shared__ float s_ab2, s_rb2, s_cb2[5];
  int tid = threadIdx.x;
  for (int t = tid; t < 2048; t += blockDim.x) { s_a1[t] = aw1[t]; s_r1[t] = rw1[t]; s_c1[t] = cw1[t]; }
  for (int t = tid; t < 160; t += blockDim.x) s_c2[t] = cw2[t];
  if (tid < 32) { s_a2[tid] = aw2[tid]; s_r2[tid] = rw2[tid];
                  s_ab1[tid] = ab1[tid]; s_rb1[tid] = rb1[tid]; s_cb1[tid] = cb1[tid]; }
  if (tid == 0) { s_ab2 = ab2[0]; s_rb2 = rb2[0]; }
  if (tid < 5) s_cb2[tid] = cb2[tid];
  __syncthreads();
  int lane = tid & 31;
  int wlocal = tid >> 5;
  int nwarps = (gridDim.x * blockDim.x) >> 5;
  for (int w = blockIdx.x * (blockDim.x >> 5) + wlocal; w < NNODES; w += nwarps) {
    float e0 = emb[(size_t)w * 64 + lane];
    float e1 = emb[(size_t)w * 64 + 32 + lane];
    float ha = s_ab1[lane], hr = s_rb1[lane], hc = s_cb1[lane];
    #pragma unroll
    for (int c = 0; c < 32; c++) {
      float x = __shfl_sync(0xffffffffu, e0, c);
      ha = fmaf(x, s_a1[c * 32 + lane], ha);
      hr = fmaf(x, s_r1[c * 32 + lane], hr);
      hc = fmaf(x, s_c1[c * 32 + lane], hc);
    }
    #pragma unroll
    for (int c = 0; c < 32; c++) {
      float x = __shfl_sync(0xffffffffu, e1, c);
      ha = fmaf(x, s_a1[(c + 32) * 32 + lane], ha);
      hr = fmaf(x, s_r1[(c + 32) * 32 + lane], hr);
      hc = fmaf(x, s_c1[(c + 32) * 32 + lane], hc);
    }
    ha = fmaxf(ha, 0.f); hr = fmaxf(hr, 0.f); hc = fmaxf(hc, 0.f);
    float pa = warp_sum(ha * s_a2[lane]);
    float pr = warp_sum(hr * s_r2[lane]);
    if (lane == 0) {
      anomaly[w] = 1.f / (1.f + __expf(-(pa + s_ab2)));
      risk[w]    = 1.f / (1.f + __expf(-(pr + s_rb2)));
    }
    #pragma unroll
    for (int o = 0; o < 5; o++) {
      float p = warp_sum(hc * s_c2[lane * 5 + o]);
      if (lane == 0) resource[(size_t)w * 5 + o] = p + s_cb2[o];
    }
  }
}

// ---------------- global mean pool + graph MLP ----------------
__global__ void k_pool(const float* __restrict__ emb, const int* __restrict__ batch,
                       const float* __restrict__ gw1, const float* __restrict__ gb1,
                       const float* __restrict__ gw2, const float* __restrict__ gb2,
                       float* __restrict__ glog) {
  __shared__ float part[256];
  __shared__ float pooled[64];
  __shared__ float hidden[32];
  __shared__ int s_lo, s_hi;
  int g = blockIdx.x;
  int tid = threadIdx.x;
  if (tid == 0) {
    int lo = 0, hi = NNODES;
    while (lo < hi) { int mid = (lo + hi) >> 1; if (batch[mid] < g) lo = mid + 1; else hi = mid; }
    int lo2 = lo, hi2 = NNODES;
    while (lo2 < hi2) { int mid = (lo2 + hi2) >> 1; if (batch[mid] <= g) lo2 = mid + 1; else hi2 = mid; }
    s_lo = lo; s_hi = lo2;
  }
  __syncthreads();
  int lo = s_lo, hi = s_hi;
  int c = tid & 63, sub = tid >> 6;
  float acc = 0.f;
  for (int i = lo + sub; i < hi; i += 4) acc += emb[(size_t)i * 64 + c];
  part[tid] = acc;
  __syncthreads();
  if (tid < 64) {
    float cnt = fmaxf((float)(hi - lo), 1.f);
    pooled[tid] = (part[tid] + part[tid + 64] + part[tid + 128] + part[tid + 192]) / cnt;
  }
  __syncthreads();
  if (tid < 32) {
    float h = gb1[tid];
    #pragma unroll
    for (int cc = 0; cc < 64; cc++) h = fmaf(pooled[cc], gw1[cc * 32 + tid], h);
    hidden[tid] = fmaxf(h, 0.f);
  }
  __syncthreads();
  if (tid < 4) {
    float o = gb2[tid];
    #pragma unroll
    for (int j = 0; j < 32; j++) o = fmaf(hidden[j], gw2[j * 4 + tid], o);
    glog[g * 4 + tid] = o;
  }
}

// ---------------- launch ----------------
extern "C" void kernel_launch(void* const* d_in, const int* in_sizes, int n_in,
                              void* d_out, int out_size) {
  const float* x     = (const float*)d_in[0];
  const int*   ei    = (const int*)d_in[1];
  const int*   batch = (const int*)d_in[2];
  const float* W1  = (const float*)d_in[3];
  const float* as1 = (const float*)d_in[4];
  const float* ad1 = (const float*)d_in[5];
  const float* b1  = (const float*)d_in[6];
  const float* W2  = (const float*)d_in[7];
  const float* as2 = (const float*)d_in[8];
  const float* ad2 = (const float*)d_in[9];
  const float* b2  = (const float*)d_in[10];
  const float* W3  = (const float*)d_in[11];
  const float* as3 = (const float*)d_in[12];
  const float* ad3 = (const float*)d_in[13];
  const float* b3  = (const float*)d_in[14];
  const float* aw1 = (const float*)d_in[15];
  const float* ab1 = (const float*)d_in[16];
  const float* aw2 = (const float*)d_in[17];
  const float* ab2 = (const float*)d_in[18];
  const float* rw1 = (const float*)d_in[19];
  const float* rb1 = (const float*)d_in[20];
  const float* rw2 = (const float*)d_in[21];
  const float* rb2 = (const float*)d_in[22];
  const float* cw1 = (const float*)d_in[23];
  const float* cb1 = (const float*)d_in[24];
  const float* cw2 = (const float*)d_in[25];
  const float* cb2 = (const float*)d_in[26];
  const float* gw1 = (const float*)d_in[27];
  const float* gb1 = (const float*)d_in[28];
  const float* gw2 = (const float*)d_in[29];
  const float* gb2 = (const float*)d_in[30];

  float* out      = (float*)d_out;
  float* emb      = out;                               // [N,64]
  float* anomaly  = emb + (size_t)NNODES * 64;         // [N]
  float* risk     = anomaly + NNODES;                  // [N]
  float* resource = risk + NNODES;                     // [N,5]
  float* glog     = resource + (size_t)NNODES * 5;     // [G,4]

  const int SMEM128 = 128 * 136 * 2 + 128 * 72 * 2 + 512;   // 53760
  const int SMEM64  = 128 * 72 * 2 + 64 * 72 * 2 + 512;     // 28160
  cudaFuncSetAttribute(k_gemm_mma<128>, cudaFuncAttributeMaxDynamicSharedMemorySize, SMEM128);
  cudaFuncSetAttribute(k_gemm_mma<64>,  cudaFuncAttributeMaxDynamicSharedMemorySize, SMEM64);

  // One-time side-stream/event/symbol setup (outside graph capture; first call
  // is the eager correctness run). Reused every call -> identical captures.
  static cudaStream_t s2 = nullptr;
  static cudaEvent_t evF, evJ, e1, e2, e3, e4, evF2, evJ2;
  static void* deg_ptr = nullptr;
  if (s2 == nullptr) {
    cudaStreamCreateWithFlags(&s2, cudaStreamNonBlocking);
    cudaEventCreateWithFlags(&evF, cudaEventDisableTiming);
    cudaEventCreateWithFlags(&evJ, cudaEventDisableTiming);
    cudaEventCreateWithFlags(&e1, cudaEventDisableTiming);
    cudaEventCreateWithFlags(&e2, cudaEventDisableTiming);
    cudaEventCreateWithFlags(&e3, cudaEventDisableTiming);
    cudaEventCreateWithFlags(&e4, cudaEventDisableTiming);
    cudaEventCreateWithFlags(&evF2, cudaEventDisableTiming);
    cudaEventCreateWithFlags(&evJ2, cudaEventDisableTiming);
    cudaGetSymbolAddress(&deg_ptr, g_deg);
  }

  dim3 gemm_full(4, YBLK_FULL);
  dim3 gemm_a(4, YBLK_A);
  dim3 gemm_b(4, YBLK_B);
  int agg_a_blocks = NODES_A / 8;                          // 3136
  int agg_b_blocks = (NNODES - NODES_A + 7) / 8;           // 3114
  int agg_full_blocks = (NNODES * 32 + 255) / 256;
  int edge_blocks = (NETOT + 255) / 256;

  // Fork: side stream builds CSR prefix while main stream does xcast + gemm1.
  cudaEventRecord(evF, 0);
  cudaStreamWaitEvent(s2, evF, 0);
  cudaMemsetAsync(deg_ptr, 0, NNODES * sizeof(int), s2);
  k_count<<<(NETOT + 255) / 256, 256, 0, s2>>>(ei);
  k_scan1<<<NBLK_SCAN, 256, 0, s2>>>();
  k_scan23<<<NBLK_SCAN, 256, 0, s2>>>();
  cudaEventRecord(evJ, s2);

  k_xcast<<<(NNODES * 32 + 255) / 256, 256>>>(x);
  k_gemm_mma<128><<<gemm_full, 256, SMEM128>>>(0, W1, as1, ad1, 0, 0);   // -> hh0

  // Join: fill needs CSR prefix (side) and gemm1 logits (main).
  cudaStreamWaitEvent(0, evJ, 0);
  k_fill_ew1<<<edge_blocks, 256>>>(ei);

  // ---- Layer 1 aggregate (reads hh0), pipelined with gemm2 (writes hh1) ----
  k_aggregate<<<agg_a_blocks, 256>>>(b1, nullptr, 1, 0, NODES_A, 0);
  cudaEventRecord(e1, 0);
  cudaStreamWaitEvent(s2, e1, 0);
  k_gemm_mma<64><<<gemm_a, 256, SMEM64, s2>>>(1, W2, as2, ad2, 0, 1);    // rows A
  cudaEventRecord(e2, s2);
  k_aggregate<<<agg_b_blocks, 256>>>(b1, nullptr, 1, NODES_A, NNODES, 0);
  k_gemm_mma<64><<<gemm_b, 256, SMEM64>>>(1, W2, as2, ad2, YBLK_A, 1);   // rows B
  cudaStreamWaitEvent(0, e2, 0);
  k_edgew<<<edge_blocks, 256>>>();

  // ---- Layer 2 aggregate (reads hh1), pipelined with gemm3 (writes hh0) ----
  k_aggregate<<<agg_a_blocks, 256>>>(b2, nullptr, 1, 0, NODES_A, 1);
  cudaEventRecord(e3, 0);
  cudaStreamWaitEvent(s2, e3, 0);
  k_gemm_mma<64><<<gemm_a, 256, SMEM64, s2>>>(1, W3, as3, ad3, 0, 0);    // rows A
  cudaEventRecord(e4, s2);
  k_aggregate<<<agg_b_blocks, 256>>>(b2, nullptr, 1, NODES_A, NNODES, 1);
  k_gemm_mma<64><<<gemm_b, 256, SMEM64>>>(1, W3, as3, ad3, YBLK_A, 0);   // rows B
  cudaStreamWaitEvent(0, e4, 0);
  k_edgew<<<edge_blocks, 256>>>();

  // ---- Layer 3 aggregate (reads hh0) -> emb fp32, no relu ----
  k_aggregate<<<agg_full_blocks, 256>>>(b3, emb, 0, 0, NNODES, 0);

  // Heads (main) and pooling (side) run concurrently on emb.
  cudaEventRecord(evF2, 0);
  cudaStreamWaitEvent(s2, evF2, 0);
  k_pool<<<NGRAPH, 256, 0, s2>>>(emb, batch, gw1, gb1, gw2, gb2, glog);
  cudaEventRecord(evJ2, s2);
  k_heads<<<HEADS_BLOCKS, 256>>>(emb, aw1, ab1, aw2, ab2,
                                 rw1, rb1, rw2, rb2,
                                 cw1, cb1, cw2, cb2,
                                 anomaly, risk, resource);
  cudaStreamWaitEvent(0, evJ2, 0);
}

// round 11
// speedup vs baseline: 1.2278x; 1.2278x over previous
#include <cuda_runtime.h>
#include <cuda_fp16.h>
#include <math.h>

#define NNODES 50000
#define NEDGES 800000
#define NETOT  (NEDGES + NNODES)
#define NGRAPH 64
#define NBLK_SCAN ((NNODES + 255) / 256)   // 196
#define HEADS_BLOCKS 592

// ---------------- scratch (device globals; no allocation allowed) ----------------
__device__ __half g_hh[NNODES * 256];    // projected features fp16; lane-interleaved
__device__ __half g_xh1[NNODES * 128];   // layer-1 input, fp16
__device__ __half g_xh[NNODES * 64];     // layer-2/3 input, fp16
__device__ float g_als[NNODES * 4];      // src attention logit per head
__device__ float g_ald[NNODES * 4];      // dst attention logit per head
__device__ int   g_deg[NNODES];
__device__ int   g_rowptr[NNODES + 1];
__device__ int   g_cursor[NNODES];
__device__ int   g_bsum[256];
__device__ uint4 g_erec[NETOT];          // AoS: {src, dst, ew01(h2), ew23(h2)}

// ---------------- helpers ----------------
__device__ __forceinline__ float warp_sum(float v) {
  #pragma unroll
  for (int o = 16; o; o >>= 1) v += __shfl_xor_sync(0xffffffffu, v, o);
  return v;
}
__device__ __forceinline__ float lrelu(float v) { return v > 0.f ? v : 0.2f * v; }

typedef unsigned long long ull;
__device__ __forceinline__ ull pack2(float x, float y) {
  ull r; asm("mov.b64 %0,{%1,%2};" : "=l"(r) : "f"(x), "f"(y)); return r;
}
__device__ __forceinline__ void ffma2(ull& d, ull a, ull b) {
  asm("fma.rn.f32x2 %0,%1,%2,%0;" : "+l"(d) : "l"(a), "l"(b));
}
__device__ __forceinline__ void fadd2(ull& d, ull a) {
  asm("add.rn.f32x2 %0,%0,%1;" : "+l"(d) : "l"(a));
}
__device__ __forceinline__ float2 unpack2(ull v) {
  float2 f; asm("mov.b64 {%0,%1},%2;" : "=f"(f.x), "=f"(f.y) : "l"(v)); return f;
}

// ---------------- CSR build ----------------
__global__ void k_count(const int* __restrict__ ei) {
  int i = blockIdx.x * blockDim.x + threadIdx.x;
  if (i >= NETOT) return;
  int d = (i < NEDGES) ? ei[NEDGES + i] : (i - NEDGES);   // self-loops appended
  atomicAdd(&g_deg[d], 1);
}

__global__ void k_scan1() {
  __shared__ int tmp[256];
  int tid = threadIdx.x;
  int i = blockIdx.x * 256 + tid;
  int v = (i < NNODES) ? g_deg[i] : 0;
  tmp[tid] = v;
  __syncthreads();
  #pragma unroll
  for (int d = 1; d < 256; d <<= 1) {
    int t = (tid >= d) ? tmp[tid - d] : 0;
    __syncthreads();
    tmp[tid] += t;
    __syncthreads();
  }
  if (i < NNODES) g_rowptr[i] = tmp[tid] - v;   // exclusive within block
  if (tid == 255) g_bsum[blockIdx.x] = tmp[255];
}

// fused: per-block offset = sum of bsum[0..bid-1], computed redundantly per block
__global__ void k_scan23() {
  __shared__ int red[256];
  int tid = threadIdx.x;
  int bid = blockIdx.x;
  int v = (tid < bid && tid < NBLK_SCAN) ? g_bsum[tid] : 0;
  red[tid] = v;
  __syncthreads();
  #pragma unroll
  for (int o = 128; o; o >>= 1) {
    if (tid < o) red[tid] += red[tid + o];
    __syncthreads();
  }
  int off = red[0];
  int i = bid * 256 + tid;
  if (i < NNODES) {
    int r = g_rowptr[i] + off;
    g_rowptr[i] = r;
    g_cursor[i] = r;
  }
  if (i == 0) g_rowptr[NNODES] = NETOT;
}

// fill CSR record AND layer-1 edge weights in one ST.128 (gemm1 logits ready)
__global__ void k_fill_ew1(const int* __restrict__ ei) {
  int i = blockIdx.x * blockDim.x + threadIdx.x;
  if (i >= NETOT) return;
  int s, d;
  if (i < NEDGES) { s = ei[i]; d = ei[NEDGES + i]; }
  else            { s = i - NEDGES; d = s; }
  int pos = atomicAdd(&g_cursor[d], 1);
  float4 as = ((const float4*)g_als)[s];
  float4 ad = ((const float4*)g_ald)[d];
  __half2 e01 = __floats2half2_rn(__expf(lrelu(as.x + ad.x)), __expf(lrelu(as.y + ad.y)));
  __half2 e23 = __floats2half2_rn(__expf(lrelu(as.z + ad.z)), __expf(lrelu(as.w + ad.w)));
  uint4 rec;
  rec.x = (unsigned)s;
  rec.y = (unsigned)d;
  rec.z = *reinterpret_cast<unsigned*>(&e01);
  rec.w = *reinterpret_cast<unsigned*>(&e23);
  g_erec[pos] = rec;
}

// ---------------- layer-1 input cast fp32 -> fp16 ----------------
__global__ void k_xcast(const float* __restrict__ x) {
  int i = blockIdx.x * blockDim.x + threadIdx.x;   // float4 index
  if (i >= NNODES * 32) return;
  float4 v = ((const float4*)x)[i];
  __half2* o = (__half2*)g_xh1;
  o[i * 2]     = __floats2half2_rn(v.x, v.y);
  o[i * 2 + 1] = __floats2half2_rn(v.z, v.w);
}

// ---------------- edge-parallel softmax weights (layers 2, 3) ----------------
__global__ void k_edgew() {
  int e = blockIdx.x * blockDim.x + threadIdx.x;
  if (e >= NETOT) return;
  int2 sd = *reinterpret_cast<const int2*>(&g_erec[e]);
  float4 as = ((const float4*)g_als)[sd.x];
  float4 ad = ((const float4*)g_ald)[sd.y];
  __half2 e01 = __floats2half2_rn(__expf(lrelu(as.x + ad.x)), __expf(lrelu(as.y + ad.y)));
  __half2 e23 = __floats2half2_rn(__expf(lrelu(as.z + ad.z)), __expf(lrelu(as.w + ad.w)));
  uint2 wv;
  wv.x = *reinterpret_cast<unsigned*>(&e01);
  wv.y = *reinterpret_cast<unsigned*>(&e23);
  *reinterpret_cast<uint2*>(reinterpret_cast<char*>(&g_erec[e]) + 8) = wv;
}

// ---------------- tensor-core GEMM + logit epilogue ----------------
__device__ __forceinline__ void ldsm4(unsigned& r0, unsigned& r1, unsigned& r2, unsigned& r3,
                                      unsigned addr) {
  asm volatile("ldmatrix.sync.aligned.m8n8.x4.shared.b16 {%0,%1,%2,%3}, [%4];"
               : "=r"(r0), "=r"(r1), "=r"(r2), "=r"(r3) : "r"(addr));
}
__device__ __forceinline__ void ldsm2t(unsigned& r0, unsigned& r1, unsigned addr) {
  asm volatile("ldmatrix.sync.aligned.m8n8.x2.trans.shared.b16 {%0,%1}, [%2];"
               : "=r"(r0), "=r"(r1) : "r"(addr));
}
__device__ __forceinline__ void mma16816(float* c, const unsigned* a, const unsigned* b) {
  asm volatile("mma.sync.aligned.m16n8k16.row.col.f32.f16.f16.f32 "
               "{%0,%1,%2,%3},{%4,%5,%6,%7},{%8,%9},{%0,%1,%2,%3};"
               : "+f"(c[0]), "+f"(c[1]), "+f"(c[2]), "+f"(c[3])
               : "r"(a[0]), "r"(a[1]), "r"(a[2]), "r"(a[3]), "r"(b[0]), "r"(b[1]));
}

template<int K>
__global__ void __launch_bounds__(256) k_gemm_mma(
    int src_sel, const float* __restrict__ W,
    const float* __restrict__ a_s, const float* __restrict__ a_d) {
  constexpr int APAD = K + 8;
  constexpr int A_BYTES = 128 * APAD * 2;
  constexpr int B_BYTES = K * 72 * 2;
  extern __shared__ __align__(16) char dyn[];
  __half* As = (__half*)dyn;
  __half* Bs = (__half*)(dyn + A_BYTES);
  float* s_as = (float*)(dyn + A_BYTES + B_BYTES);
  float* s_ad = s_as + 64;
  float* red_s = (float*)dyn;                // overlay after mma: [128][2]
  float* red_d = (float*)(dyn + 1024);

  const __half* __restrict__ X = (src_sel == 0) ? g_xh1 : g_xh;
  int tid = threadIdx.x;
  int lane = tid & 31, wid = tid >> 5;
  int warp_m = wid >> 1, warp_n = wid & 1;
  int hd = blockIdx.x;
  int col0 = hd * 64;
  int row0 = blockIdx.y * 128;

  if (tid < 64) { s_as[tid] = a_s[col0 + tid]; s_ad[tid] = a_d[col0 + tid]; }

  constexpr int A_IT = 128 * K / 8 / 256;
  #pragma unroll
  for (int it = 0; it < A_IT; it++) {
    int idx = tid + it * 256;
    int r = idx / (K / 8), c8 = idx % (K / 8);
    uint4 v = make_uint4(0, 0, 0, 0);
    if (row0 + r < NNODES)
      v = *(const uint4*)&X[(size_t)(row0 + r) * K + c8 * 8];
    *(uint4*)&As[r * APAD + c8 * 8] = v;
  }
  constexpr int B_IT = K * 16 / 256;
  #pragma unroll
  for (int it = 0; it < B_IT; it++) {
    int idx = tid + it * 256;
    int k = idx >> 4, c4 = idx & 15;
    float4 v = *(const float4*)&W[(size_t)k * 256 + col0 + c4 * 4];
    __half2* o = (__half2*)&Bs[k * 72 + c4 * 4];
    o[0] = __floats2half2_rn(v.x, v.y);
    o[1] = __floats2half2_rn(v.z, v.w);
  }
  __syncthreads();

  unsigned As_u = (unsigned)__cvta_generic_to_shared(As);
  unsigned Bs_u = (unsigned)__cvta_generic_to_shared(Bs);
  unsigned a_base = As_u + ((warp_m * 32 + (lane & 15)) * APAD + (lane >> 4) * 8) * 2;
  unsigned b_base = Bs_u + ((lane & 15) * 72 + warp_n * 32) * 2;

  float acc[2][4][4];
  #pragma unroll
  for (int mt = 0; mt < 2; mt++)
    #pragma unroll
    for (int nt = 0; nt < 4; nt++)
      #pragma unroll
      for (int q = 0; q < 4; q++) acc[mt][nt][q] = 0.f;

  #pragma unroll
  for (int ks = 0; ks < K / 16; ks++) {
    unsigned a[2][4], b[4][2];
    #pragma unroll
    for (int mt = 0; mt < 2; mt++)
      ldsm4(a[mt][0], a[mt][1], a[mt][2], a[mt][3],
            a_base + (mt * 16 * APAD + ks * 16) * 2);
    #pragma unroll
    for (int nt = 0; nt < 4; nt++)
      ldsm2t(b[nt][0], b[nt][1], b_base + (ks * 16 * 72 + nt * 8) * 2);
    #pragma unroll
    for (int mt = 0; mt < 2; mt++)
      #pragma unroll
      for (int nt = 0; nt < 4; nt++)
        mma16816(acc[mt][nt], a[mt], b[nt]);
  }
  __syncthreads();   // reds overlay As

  int quad = lane >> 2, qid = lane & 3;
  #pragma unroll
  for (int mt = 0; mt < 2; mt++) {
    #pragma unroll
    for (int rh = 0; rh < 2; rh++) {
      int lr = warp_m * 32 + mt * 16 + rh * 8 + quad;
      int row = row0 + lr;
      float ss = 0.f, sd = 0.f;
      #pragma unroll
      for (int nt = 0; nt < 4; nt++) {
        float v0 = acc[mt][nt][rh * 2 + 0];
        float v1 = acc[mt][nt][rh * 2 + 1];
        int c = warp_n * 32 + nt * 8 + qid * 2;     // local even channel
        ss = fmaf(v0, s_as[c], fmaf(v1, s_as[c + 1], ss));
        sd = fmaf(v0, s_ad[c], fmaf(v1, s_ad[c + 1], sd));
        if (row < NNODES)   // lane-interleaved layout: 8*(c/2) + 2*hd
          *(__half2*)&g_hh[(size_t)row * 256 + c * 4 + hd * 2] = __floats2half2_rn(v0, v1);
      }
      ss += __shfl_xor_sync(0xffffffffu, ss, 1);
      ss += __shfl_xor_sync(0xffffffffu, ss, 2);
      sd += __shfl_xor_sync(0xffffffffu, sd, 1);
      sd += __shfl_xor_sync(0xffffffffu, sd, 2);
      if (qid == 0) { red_s[lr * 2 + warp_n] = ss; red_d[lr * 2 + warp_n] = sd; }
    }
  }
  __syncthreads();
  if (tid < 128) {
    int row = row0 + tid;
    if (row < NNODES) {
      g_als[row * 4 + hd] = red_s[tid * 2] + red_s[tid * 2 + 1];
      g_ald[row * 4 + hd] = red_d[tid * 2] + red_d[tid * 2 + 1];
    }
  }
}

// ---------------- GAT aggregate (one warp per node, full range, runs alone) ----------------
// lane l owns channels {2l, 2l+1} of all 4 heads: one LDG.128 feature gather +
// one broadcast LDG.128 AoS metadata record per edge.
__global__ void k_aggregate(const float* __restrict__ bias, float* __restrict__ xout,
                            int fp16_relu) {
  int w = (blockIdx.x * blockDim.x + threadIdx.x) >> 5;
  int lane = threadIdx.x & 31;
  if (w >= NNODES) return;
  int beg = g_rowptr[w], end = g_rowptr[w + 1];
  const uint4* __restrict__ H4 = (const uint4*)g_hh;     // 32 uint4 per row
  const uint4* __restrict__ REC = (const uint4*)g_erec;

  ull acc0 = 0, acc1 = 0, acc2 = 0, acc3 = 0;
  ull dd01 = 0, dd23 = 0;

#define EDGE_ACC(hv, rec)                                                 \
  do {                                                                    \
    float2 w01 = __half22float2(*reinterpret_cast<const __half2*>(&(rec).z)); \
    float2 w23 = __half22float2(*reinterpret_cast<const __half2*>(&(rec).w)); \
    fadd2(dd01, pack2(w01.x, w01.y));                                     \
    fadd2(dd23, pack2(w23.x, w23.y));                                     \
    float2 f0 = __half22float2(*(__half2*)&(hv).x);                       \
    float2 f1 = __half22float2(*(__half2*)&(hv).y);                       \
    float2 f2 = __half22float2(*(__half2*)&(hv).z);                       \
    float2 f3 = __half22float2(*(__half2*)&(hv).w);                       \
    ffma2(acc0, pack2(f0.x, f0.y), pack2(w01.x, w01.x));                  \
    ffma2(acc1, pack2(f1.x, f1.y), pack2(w01.y, w01.y));                  \
    ffma2(acc2, pack2(f2.x, f2.y), pack2(w23.x, w23.x));                  \
    ffma2(acc3, pack2(f3.x, f3.y), pack2(w23.y, w23.y));                  \
  } while (0)

  int e = beg;
  for (; e + 4 <= end; e += 4) {
    uint4 r0 = REC[e], r1 = REC[e + 1], r2 = REC[e + 2], r3 = REC[e + 3];
    uint4 h0 = H4[(size_t)r0.x * 32 + lane];
    uint4 h1 = H4[(size_t)r1.x * 32 + lane];
    uint4 h2 = H4[(size_t)r2.x * 32 + lane];
    uint4 h3 = H4[(size_t)r3.x * 32 + lane];
    EDGE_ACC(h0, r0);
    EDGE_ACC(h1, r1);
    EDGE_ACC(h2, r2);
    EDGE_ACC(h3, r3);
  }
  for (; e < end; e++) {
    uint4 rv = REC[e];
    uint4 hv = H4[(size_t)rv.x * 32 + lane];
    EDGE_ACC(hv, rv);
  }
#undef EDGE_ACC

  float2 d01 = unpack2(dd01), d23 = unpack2(dd23);
  float2 a0 = unpack2(acc0), a1 = unpack2(acc1), a2 = unpack2(acc2), a3 = unpack2(acc3);
  float r0 = 1.f / d01.x, r1 = 1.f / d01.y, r2 = 1.f / d23.x, r3 = 1.f / d23.y;
  float2 bv = ((const float2*)bias)[lane];
  float2 o;
  o.x = (a0.x * r0 + a1.x * r1 + a2.x * r2 + a3.x * r3) * 0.25f + bv.x;
  o.y = (a0.y * r0 + a1.y * r1 + a2.y * r2 + a3.y * r3) * 0.25f + bv.y;
  if (fp16_relu) {
    o.x = fmaxf(o.x, 0.f); o.y = fmaxf(o.y, 0.f);
    ((__half2*)g_xh)[(size_t)w * 32 + lane] = __floats2half2_rn(o.x, o.y);
  } else {
    ((float2*)xout)[(size_t)w * 32 + lane] = o;
  }
}

// ---------------- per-node MLP heads (grid-stride; weights loaded once per block) ----------------
__global__ void __launch_bounds__(256) k_heads(
                        const float* __restrict__ emb,
                        const float* __restrict__ aw1, const float* __restrict__ ab1,
                        const float* __restrict__ aw2, const float* __restrict__ ab2,
                        const float* __restrict__ rw1, const float* __restrict__ rb1,
                        const float* __restrict__ rw2, const float* __restrict__ rb2,
                        const float* __restrict__ cw1, const float* __restrict__ cb1,
                        const float* __restrict__ cw2, const float* __restrict__ cb2,
                        float* __restrict__ anomaly, float* __restrict__ risk,
                        float* __restrict__ resource) {
  __shared__ float s_a1[2048], s_r1[2048], s_c1[2048];
  __shared__ float s_a2[32], s_r2[32], s_c2[160];
  __shared__ float s_ab1[32], s_rb1[32], s_cb1[32];
  __shared__ float s_ab2, s_rb2, s_cb2[5];
  int tid = threadIdx.x;
  for (int t = tid; t < 2048; t += blockDim.x) { s_a1[t] = aw1[t]; s_r1[t] = rw1[t]; s_c1[t] = cw1[t]; }
  for (int t = tid; t < 160; t += blockDim.x) s_c2[t] = cw2[t];
  if (tid < 32) { s_a2[tid] = aw2[tid]; s_r2[tid] = rw2[tid];
                  s_ab1[tid] = ab1[tid]; s_rb1[tid] = rb1[tid]; s_cb1[tid] = cb1[tid]; }
  if (tid == 0) { s_ab2 = ab2[0]; s_rb2 = rb2[0]; }
  if (tid < 5) s_cb2[tid] = cb2[tid];
  __syncthreads();
  int lane = tid & 31;
  int wlocal = tid >> 5;
  int nwarps = (gridDim.x * blockDim.x) >> 5;
  for (int w = blockIdx.x * (blockDim.x >> 5) + wlocal; w < NNODES; w += nwarps) {
    float e0 = emb[(size_t)w * 64 + lane];
    float e1 = emb[(size_t)w * 64 + 32 + lane];
    float ha = s_ab1[lane], hr = s_rb1[lane], hc = s_cb1[lane];
    #pragma unroll
    for (int c = 0; c < 32; c++) {
      float x = __shfl_sync(0xffffffffu, e0, c);
      ha = fmaf(x, s_a1[c * 32 + lane], ha);
      hr = fmaf(x, s_r1[c * 32 + lane], hr);
      hc = fmaf(x, s_c1[c * 32 + lane], hc);
    }
    #pragma unroll
    for (int c = 0; c < 32; c++) {
      float x = __shfl_sync(0xffffffffu, e1, c);
      ha = fmaf(x, s_a1[(c + 32) * 32 + lane], ha);
      hr = fmaf(x, s_r1[(c + 32) * 32 + lane], hr);
      hc = fmaf(x, s_c1[(c + 32) * 32 + lane], hc);
    }
    ha = fmaxf(ha, 0.f); hr = fmaxf(hr, 0.f); hc = fmaxf(hc, 0.f);
    float pa = warp_sum(ha * s_a2[lane]);
    float pr = warp_sum(hr * s_r2[lane]);
    if (lane == 0) {
      anomaly[w] = 1.f / (1.f + __expf(-(pa + s_ab2)));
      risk[w]    = 1.f / (1.f + __expf(-(pr + s_rb2)));
    }
    #pragma unroll
    for (int o = 0; o < 5; o++) {
      float p = warp_sum(hc * s_c2[lane * 5 + o]);
      if (lane == 0) resource[(size_t)w * 5 + o] = p + s_cb2[o];
    }
  }
}

// ---------------- global mean pool + graph MLP ----------------
__global__ void k_pool(const float* __restrict__ emb, const int* __restrict__ batch,
                       const float* __restrict__ gw1, const float* __restrict__ gb1,
                       const float* __restrict__ gw2, const float* __restrict__ gb2,
                       float* __restrict__ glog) {
  __shared__ float part[256];
  __shared__ float pooled[64];
  __shared__ float hidden[32];
  __shared__ int s_lo, s_hi;
  int g = blockIdx.x;
  int tid = threadIdx.x;
  if (tid == 0) {
    int lo = 0, hi = NNODES;
    while (lo < hi) { int mid = (lo + hi) >> 1; if (batch[mid] < g) lo = mid + 1; else hi = mid; }
    int lo2 = lo, hi2 = NNODES;
    while (lo2 < hi2) { int mid = (lo2 + hi2) >> 1; if (batch[mid] <= g) lo2 = mid + 1; else hi2 = mid; }
    s_lo = lo; s_hi = lo2;
  }
  __syncthreads();
  int lo = s_lo, hi = s_hi;
  int c = tid & 63, sub = tid >> 6;
  float acc = 0.f;
  for (int i = lo + sub; i < hi; i += 4) acc += emb[(size_t)i * 64 + c];
  part[tid] = acc;
  __syncthreads();
  if (tid < 64) {
    float cnt = fmaxf((float)(hi - lo), 1.f);
    pooled[tid] = (part[tid] + part[tid + 64] + part[tid + 128] + part[tid + 192]) / cnt;
  }
  __syncthreads();
  if (tid < 32) {
    float h = gb1[tid];
    #pragma unroll
    for (int cc = 0; cc < 64; cc++) h = fmaf(pooled[cc], gw1[cc * 32 + tid], h);
    hidden[tid] = fmaxf(h, 0.f);
  }
  __syncthreads();
  if (tid < 4) {
    float o = gb2[tid];
    #pragma unroll
    for (int j = 0; j < 32; j++) o = fmaf(hidden[j], gw2[j * 4 + tid], o);
    glog[g * 4 + tid] = o;
  }
}

// ---------------- launch ----------------
extern "C" void kernel_launch(void* const* d_in, const int* in_sizes, int n_in,
                              void* d_out, int out_size) {
  const float* x     = (const float*)d_in[0];
  const int*   ei    = (const int*)d_in[1];
  const int*   batch = (const int*)d_in[2];
  const float* W1  = (const float*)d_in[3];
  const float* as1 = (const float*)d_in[4];
  const float* ad1 = (const float*)d_in[5];
  const float* b1  = (const float*)d_in[6];
  const float* W2  = (const float*)d_in[7];
  const float* as2 = (const float*)d_in[8];
  const float* ad2 = (const float*)d_in[9];
  const float* b2  = (const float*)d_in[10];
  const float* W3  = (const float*)d_in[11];
  const float* as3 = (const float*)d_in[12];
  const float* ad3 = (const float*)d_in[13];
  const float* b3  = (const float*)d_in[14];
  const float* aw1 = (const float*)d_in[15];
  const float* ab1 = (const float*)d_in[16];
  const float* aw2 = (const float*)d_in[17];
  const float* ab2 = (const float*)d_in[18];
  const float* rw1 = (const float*)d_in[19];
  const float* rb1 = (const float*)d_in[20];
  const float* rw2 = (const float*)d_in[21];
  const float* rb2 = (const float*)d_in[22];
  const float* cw1 = (const float*)d_in[23];
  const float* cb1 = (const float*)d_in[24];
  const float* cw2 = (const float*)d_in[25];
  const float* cb2 = (const float*)d_in[26];
  const float* gw1 = (const float*)d_in[27];
  const float* gb1 = (const float*)d_in[28];
  const float* gw2 = (const float*)d_in[29];
  const float* gb2 = (const float*)d_in[30];

  float* out      = (float*)d_out;
  float* emb      = out;                               // [N,64]
  float* anomaly  = emb + (size_t)NNODES * 64;         // [N]
  float* risk     = anomaly + NNODES;                  // [N]
  float* resource = risk + NNODES;                     // [N,5]
  float* glog     = resource + (size_t)NNODES * 5;     // [G,4]

  const int SMEM128 = 128 * 136 * 2 + 128 * 72 * 2 + 512;   // 53760
  const int SMEM64  = 128 * 72 * 2 + 64 * 72 * 2 + 512;     // 28160
  cudaFuncSetAttribute(k_gemm_mma<128>, cudaFuncAttributeMaxDynamicSharedMemorySize, SMEM128);
  cudaFuncSetAttribute(k_gemm_mma<64>,  cudaFuncAttributeMaxDynamicSharedMemorySize, SMEM64);

  // One-time side-stream/event/symbol setup (outside graph capture; first call
  // is the eager correctness run). Reused every call -> identical captures.
  static cudaStream_t s2 = nullptr;
  static cudaEvent_t evF, evJ, evF2, evJ2;
  static void* deg_ptr = nullptr;
  if (s2 == nullptr) {
    cudaStreamCreateWithFlags(&s2, cudaStreamNonBlocking);
    cudaEventCreateWithFlags(&evF, cudaEventDisableTiming);
    cudaEventCreateWithFlags(&evJ, cudaEventDisableTiming);
    cudaEventCreateWithFlags(&evF2, cudaEventDisableTiming);
    cudaEventCreateWithFlags(&evJ2, cudaEventDisableTiming);
    cudaGetSymbolAddress(&deg_ptr, g_deg);
  }

  dim3 gemm_grid(4, (NNODES + 127) / 128);
  int warp_blocks = (NNODES * 32 + 255) / 256;
  int edge_blocks = (NETOT + 255) / 256;

  // Fork: side stream builds CSR prefix while main stream does xcast + gemm1.
  cudaEventRecord(evF, 0);
  cudaStreamWaitEvent(s2, evF, 0);
  cudaMemsetAsync(deg_ptr, 0, NNODES * sizeof(int), s2);
  k_count<<<(NETOT + 255) / 256, 256, 0, s2>>>(ei);
  k_scan1<<<NBLK_SCAN, 256, 0, s2>>>();
  k_scan23<<<NBLK_SCAN, 256, 0, s2>>>();
  cudaEventRecord(evJ, s2);

  k_xcast<<<(NNODES * 32 + 255) / 256, 256>>>(x);
  k_gemm_mma<128><<<gemm_grid, 256, SMEM128>>>(0, W1, as1, ad1);

  // Join: fill needs CSR prefix (side) and gemm1 logits (main).
  cudaStreamWaitEvent(0, evJ, 0);
  k_fill_ew1<<<edge_blocks, 256>>>(ei);

  // Layer 1 (aggregate runs alone, full device)
  k_aggregate<<<warp_blocks, 256>>>(b1, nullptr, 1);      // -> g_xh fp16 + relu
  // Layer 2
  k_gemm_mma<64><<<gemm_grid, 256, SMEM64>>>(1, W2, as2, ad2);
  k_edgew<<<edge_blocks, 256>>>();
  k_aggregate<<<warp_blocks, 256>>>(b2, nullptr, 1);      // -> g_xh fp16 + relu
  // Layer 3
  k_gemm_mma<64><<<gemm_grid, 256, SMEM64>>>(1, W3, as3, ad3);
  k_edgew<<<edge_blocks, 256>>>();
  k_aggregate<<<warp_blocks, 256>>>(b3, emb, 0);          // -> emb fp32, no relu

  // Heads (main) and pooling (side) run concurrently on emb.
  cudaEventRecord(evF2, 0);
  cudaStreamWaitEvent(s2, evF2, 0);
  k_pool<<<NGRAPH, 256, 0, s2>>>(emb, batch, gw1, gb1, gw2, gb2, glog);
  cudaEventRecord(evJ2, s2);
  k_heads<<<HEADS_BLOCKS, 256>>>(emb, aw1, ab1, aw2, ab2,
                                 rw1, rb1, rw2, rb2,
                                 cw1, cb1, cw2, cb2,
                                 anomaly, risk, resource);
  cudaStreamWaitEvent(0, evJ2, 0);
}

// round 12
// speedup vs baseline: 1.2352x; 1.0060x over previous
#include <cuda_runtime.h>
#include <cuda_fp16.h>
#include <math.h>

#define NNODES 50000
#define NEDGES 800000
#define NETOT  (NEDGES + NNODES)
#define NGRAPH 64
#define NBLK_SCAN ((NNODES + 255) / 256)   // 196
#define HEADS_BLOCKS 592

// ---------------- scratch (device globals; no allocation allowed) ----------------
__device__ __half g_hh[NNODES * 256];    // projected features fp16; lane-interleaved
__device__ __half g_xh[NNODES * 64];     // layer-2/3 input, fp16
__device__ float g_als[NNODES * 4];      // src attention logit per head
__device__ float g_ald[NNODES * 4];      // dst attention logit per head
__device__ int   g_deg[NNODES];
__device__ int   g_rowptr[NNODES + 1];
__device__ int   g_cursor[NNODES];
__device__ int   g_bsum[256];
__device__ uint4 g_erec[NETOT];          // AoS: {src, dst, ew01(h2), ew23(h2)}

// ---------------- helpers ----------------
__device__ __forceinline__ float warp_sum(float v) {
  #pragma unroll
  for (int o = 16; o; o >>= 1) v += __shfl_xor_sync(0xffffffffu, v, o);
  return v;
}
__device__ __forceinline__ float lrelu(float v) { return v > 0.f ? v : 0.2f * v; }

typedef unsigned long long ull;
__device__ __forceinline__ ull pack2(float x, float y) {
  ull r; asm("mov.b64 %0,{%1,%2};" : "=l"(r) : "f"(x), "f"(y)); return r;
}
__device__ __forceinline__ void ffma2(ull& d, ull a, ull b) {
  asm("fma.rn.f32x2 %0,%1,%2,%0;" : "+l"(d) : "l"(a), "l"(b));
}
__device__ __forceinline__ void fadd2(ull& d, ull a) {
  asm("add.rn.f32x2 %0,%0,%1;" : "+l"(d) : "l"(a));
}
__device__ __forceinline__ float2 unpack2(ull v) {
  float2 f; asm("mov.b64 {%0,%1},%2;" : "=f"(f.x), "=f"(f.y) : "l"(v)); return f;
}

// ---------------- CSR build ----------------
// real edges only (self-loops folded into scan1 as +1); 4 edges per thread
__global__ void k_count(const int* __restrict__ ei) {
  int t = blockIdx.x * blockDim.x + threadIdx.x;
  if (t >= NEDGES / 4) return;
  int4 d4 = ((const int4*)(ei + NEDGES))[t];
  atomicAdd(&g_deg[d4.x], 1);
  atomicAdd(&g_deg[d4.y], 1);
  atomicAdd(&g_deg[d4.z], 1);
  atomicAdd(&g_deg[d4.w], 1);
}

__global__ void k_scan1() {
  __shared__ int tmp[256];
  int tid = threadIdx.x;
  int i = blockIdx.x * 256 + tid;
  int v = (i < NNODES) ? g_deg[i] + 1 : 0;   // +1 = self-loop
  tmp[tid] = v;
  __syncthreads();
  #pragma unroll
  for (int d = 1; d < 256; d <<= 1) {
    int t = (tid >= d) ? tmp[tid - d] : 0;
    __syncthreads();
    tmp[tid] += t;
    __syncthreads();
  }
  if (i < NNODES) g_rowptr[i] = tmp[tid] - v;   // exclusive within block
  if (tid == 255) g_bsum[blockIdx.x] = tmp[255];
}

// fused: per-block offset = sum of bsum[0..bid-1], computed redundantly per block
__global__ void k_scan23() {
  __shared__ int red[256];
  int tid = threadIdx.x;
  int bid = blockIdx.x;
  int v = (tid < bid && tid < NBLK_SCAN) ? g_bsum[tid] : 0;
  red[tid] = v;
  __syncthreads();
  #pragma unroll
  for (int o = 128; o; o >>= 1) {
    if (tid < o) red[tid] += red[tid + o];
    __syncthreads();
  }
  int off = red[0];
  int i = bid * 256 + tid;
  if (i < NNODES) {
    int r = g_rowptr[i] + off;
    g_rowptr[i] = r;
    g_cursor[i] = r;
  }
  if (i == 0) g_rowptr[NNODES] = NETOT;
}

// fill CSR record AND layer-1 edge weights; 2 edges per thread (independent chains)
__device__ __forceinline__ void fill_one(int s, int d) {
  int pos = atomicAdd(&g_cursor[d], 1);
  float4 as = ((const float4*)g_als)[s];
  float4 ad = ((const float4*)g_ald)[d];
  __half2 e01 = __floats2half2_rn(__expf(lrelu(as.x + ad.x)), __expf(lrelu(as.y + ad.y)));
  __half2 e23 = __floats2half2_rn(__expf(lrelu(as.z + ad.z)), __expf(lrelu(as.w + ad.w)));
  uint4 rec;
  rec.x = (unsigned)s;
  rec.y = (unsigned)d;
  rec.z = *reinterpret_cast<unsigned*>(&e01);
  rec.w = *reinterpret_cast<unsigned*>(&e23);
  g_erec[pos] = rec;
}

__global__ void k_fill_ew1(const int* __restrict__ ei) {
  int j = blockIdx.x * blockDim.x + threadIdx.x;
  if (j >= NETOT / 2) return;
  int e0 = 2 * j;
  if (e0 < NEDGES) {   // NEDGES even -> pair never straddles
    int2 ss = *(const int2*)&ei[e0];
    int2 dd = *(const int2*)&ei[NEDGES + e0];
    fill_one(ss.x, dd.x);
    fill_one(ss.y, dd.y);
  } else {
    int n0 = e0 - NEDGES;
    fill_one(n0, n0);
    fill_one(n0 + 1, n0 + 1);
  }
}

// ---------------- edge-parallel softmax weights (layers 2, 3); 2 edges/thread ----------------
__device__ __forceinline__ void edgew_one(int e) {
  int2 sd = *reinterpret_cast<const int2*>(&g_erec[e]);
  float4 as = ((const float4*)g_als)[sd.x];
  float4 ad = ((const float4*)g_ald)[sd.y];
  __half2 e01 = __floats2half2_rn(__expf(lrelu(as.x + ad.x)), __expf(lrelu(as.y + ad.y)));
  __half2 e23 = __floats2half2_rn(__expf(lrelu(as.z + ad.z)), __expf(lrelu(as.w + ad.w)));
  uint2 wv;
  wv.x = *reinterpret_cast<unsigned*>(&e01);
  wv.y = *reinterpret_cast<unsigned*>(&e23);
  *reinterpret_cast<uint2*>(reinterpret_cast<char*>(&g_erec[e]) + 8) = wv;
}

__global__ void k_edgew() {
  int j = blockIdx.x * blockDim.x + threadIdx.x;
  if (j >= NETOT / 2) return;
  edgew_one(2 * j);
  edgew_one(2 * j + 1);
}

// ---------------- tensor-core GEMM + logit epilogue ----------------
__device__ __forceinline__ void ldsm4(unsigned& r0, unsigned& r1, unsigned& r2, unsigned& r3,
                                      unsigned addr) {
  asm volatile("ldmatrix.sync.aligned.m8n8.x4.shared.b16 {%0,%1,%2,%3}, [%4];"
               : "=r"(r0), "=r"(r1), "=r"(r2), "=r"(r3) : "r"(addr));
}
__device__ __forceinline__ void ldsm2t(unsigned& r0, unsigned& r1, unsigned addr) {
  asm volatile("ldmatrix.sync.aligned.m8n8.x2.trans.shared.b16 {%0,%1}, [%2];"
               : "=r"(r0), "=r"(r1) : "r"(addr));
}
__device__ __forceinline__ void mma16816(float* c, const unsigned* a, const unsigned* b) {
  asm volatile("mma.sync.aligned.m16n8k16.row.col.f32.f16.f16.f32 "
               "{%0,%1,%2,%3},{%4,%5,%6,%7},{%8,%9},{%0,%1,%2,%3};"
               : "+f"(c[0]), "+f"(c[1]), "+f"(c[2]), "+f"(c[3])
               : "r"(a[0]), "r"(a[1]), "r"(a[2]), "r"(a[3]), "r"(b[0]), "r"(b[1]));
}

// CVT=true: A loaded from fp32 Xf (layer 1, xcast fused); else fp16 g_xh.
template<int K, bool CVT>
__global__ void __launch_bounds__(256) k_gemm_mma(
    const float* __restrict__ Xf, const float* __restrict__ W,
    const float* __restrict__ a_s, const float* __restrict__ a_d) {
  constexpr int APAD = K + 8;
  constexpr int A_BYTES = 128 * APAD * 2;
  constexpr int B_BYTES = K * 72 * 2;
  extern __shared__ __align__(16) char dyn[];
  __half* As = (__half*)dyn;
  __half* Bs = (__half*)(dyn + A_BYTES);
  float* s_as = (float*)(dyn + A_BYTES + B_BYTES);
  float* s_ad = s_as + 64;
  float* red_s = (float*)dyn;                // overlay after mma: [128][2]
  float* red_d = (float*)(dyn + 1024);

  int tid = threadIdx.x;
  int lane = tid & 31, wid = tid >> 5;
  int warp_m = wid >> 1, warp_n = wid & 1;
  int hd = blockIdx.x;
  int col0 = hd * 64;
  int row0 = blockIdx.y * 128;

  if (tid < 64) { s_as[tid] = a_s[col0 + tid]; s_ad[tid] = a_d[col0 + tid]; }

  if (CVT) {
    // fp32 A: 128 rows x K floats; K/4 float4 per row
    constexpr int A_IT = 128 * (K / 4) / 256;
    #pragma unroll
    for (int it = 0; it < A_IT; it++) {
      int idx = tid + it * 256;
      int r = idx / (K / 4), c4 = idx % (K / 4);
      float4 v = make_float4(0.f, 0.f, 0.f, 0.f);
      if (row0 + r < NNODES)
        v = *(const float4*)&Xf[(size_t)(row0 + r) * K + c4 * 4];
      __half2 h01 = __floats2half2_rn(v.x, v.y);
      __half2 h23 = __floats2half2_rn(v.z, v.w);
      uint2 st;
      st.x = *reinterpret_cast<unsigned*>(&h01);
      st.y = *reinterpret_cast<unsigned*>(&h23);
      *(uint2*)&As[r * APAD + c4 * 4] = st;
    }
  } else {
    constexpr int A_IT = 128 * K / 8 / 256;
    #pragma unroll
    for (int it = 0; it < A_IT; it++) {
      int idx = tid + it * 256;
      int r = idx / (K / 8), c8 = idx % (K / 8);
      uint4 v = make_uint4(0, 0, 0, 0);
      if (row0 + r < NNODES)
        v = *(const uint4*)&g_xh[(size_t)(row0 + r) * K + c8 * 8];
      *(uint4*)&As[r * APAD + c8 * 8] = v;
    }
  }
  constexpr int B_IT = K * 16 / 256;
  #pragma unroll
  for (int it = 0; it < B_IT; it++) {
    int idx = tid + it * 256;
    int k = idx >> 4, c4 = idx & 15;
    float4 v = *(const float4*)&W[(size_t)k * 256 + col0 + c4 * 4];
    __half2* o = (__half2*)&Bs[k * 72 + c4 * 4];
    o[0] = __floats2half2_rn(v.x, v.y);
    o[1] = __floats2half2_rn(v.z, v.w);
  }
  __syncthreads();

  unsigned As_u = (unsigned)__cvta_generic_to_shared(As);
  unsigned Bs_u = (unsigned)__cvta_generic_to_shared(Bs);
  unsigned a_base = As_u + ((warp_m * 32 + (lane & 15)) * APAD + (lane >> 4) * 8) * 2;
  unsigned b_base = Bs_u + ((lane & 15) * 72 + warp_n * 32) * 2;

  float acc[2][4][4];
  #pragma unroll
  for (int mt = 0; mt < 2; mt++)
    #pragma unroll
    for (int nt = 0; nt < 4; nt++)
      #pragma unroll
      for (int q = 0; q < 4; q++) acc[mt][nt][q] = 0.f;

  #pragma unroll
  for (int ks = 0; ks < K / 16; ks++) {
    unsigned a[2][4], b[4][2];
    #pragma unroll
    for (int mt = 0; mt < 2; mt++)
      ldsm4(a[mt][0], a[mt][1], a[mt][2], a[mt][3],
            a_base + (mt * 16 * APAD + ks * 16) * 2);
    #pragma unroll
    for (int nt = 0; nt < 4; nt++)
      ldsm2t(b[nt][0], b[nt][1], b_base + (ks * 16 * 72 + nt * 8) * 2);
    #pragma unroll
    for (int mt = 0; mt < 2; mt++)
      #pragma unroll
      for (int nt = 0; nt < 4; nt++)
        mma16816(acc[mt][nt], a[mt], b[nt]);
  }
  __syncthreads();   // reds overlay As

  int quad = lane >> 2, qid = lane & 3;
  #pragma unroll
  for (int mt = 0; mt < 2; mt++) {
    #pragma unroll
    for (int rh = 0; rh < 2; rh++) {
      int lr = warp_m * 32 + mt * 16 + rh * 8 + quad;
      int row = row0 + lr;
      float ss = 0.f, sd = 0.f;
      #pragma unroll
      for (int nt = 0; nt < 4; nt++) {
        float v0 = acc[mt][nt][rh * 2 + 0];
        float v1 = acc[mt][nt][rh * 2 + 1];
        int c = warp_n * 32 + nt * 8 + qid * 2;     // local even channel
        ss = fmaf(v0, s_as[c], fmaf(v1, s_as[c + 1], ss));
        sd = fmaf(v0, s_ad[c], fmaf(v1, s_ad[c + 1], sd));
        if (row < NNODES)   // lane-interleaved layout: 8*(c/2) + 2*hd
          *(__half2*)&g_hh[(size_t)row * 256 + c * 4 + hd * 2] = __floats2half2_rn(v0, v1);
      }
      ss += __shfl_xor_sync(0xffffffffu, ss, 1);
      ss += __shfl_xor_sync(0xffffffffu, ss, 2);
      sd += __shfl_xor_sync(0xffffffffu, sd, 1);
      sd += __shfl_xor_sync(0xffffffffu, sd, 2);
      if (qid == 0) { red_s[lr * 2 + warp_n] = ss; red_d[lr * 2 + warp_n] = sd; }
    }
  }
  __syncthreads();
  if (tid < 128) {
    int row = row0 + tid;
    if (row < NNODES) {
      g_als[row * 4 + hd] = red_s[tid * 2] + red_s[tid * 2 + 1];
      g_ald[row * 4 + hd] = red_d[tid * 2] + red_d[tid * 2 + 1];
    }
  }
}

// ---------------- GAT aggregate (one warp per node, full range, runs alone) ----------------
__global__ void k_aggregate(const float* __restrict__ bias, float* __restrict__ xout,
                            int fp16_relu) {
  int w = (blockIdx.x * blockDim.x + threadIdx.x) >> 5;
  int lane = threadIdx.x & 31;
  if (w >= NNODES) return;
  int beg = g_rowptr[w], end = g_rowptr[w + 1];
  const uint4* __restrict__ H4 = (const uint4*)g_hh;     // 32 uint4 per row
  const uint4* __restrict__ REC = (const uint4*)g_erec;

  ull acc0 = 0, acc1 = 0, acc2 = 0, acc3 = 0;
  ull dd01 = 0, dd23 = 0;

#define EDGE_ACC(hv, rec)                                                 \
  do {                                                                    \
    float2 w01 = __half22float2(*reinterpret_cast<const __half2*>(&(rec).z)); \
    float2 w23 = __half22float2(*reinterpret_cast<const __half2*>(&(rec).w)); \
    fadd2(dd01, pack2(w01.x, w01.y));                                     \
    fadd2(dd23, pack2(w23.x, w23.y));                                     \
    float2 f0 = __half22float2(*(__half2*)&(hv).x);                       \
    float2 f1 = __half22float2(*(__half2*)&(hv).y);                       \
    float2 f2 = __half22float2(*(__half2*)&(hv).z);                       \
    float2 f3 = __half22float2(*(__half2*)&(hv).w);                       \
    ffma2(acc0, pack2(f0.x, f0.y), pack2(w01.x, w01.x));                  \
    ffma2(acc1, pack2(f1.x, f1.y), pack2(w01.y, w01.y));                  \
    ffma2(acc2, pack2(f2.x, f2.y), pack2(w23.x, w23.x));                  \
    ffma2(acc3, pack2(f3.x, f3.y), pack2(w23.y, w23.y));                  \
  } while (0)

  int e = beg;
  for (; e + 4 <= end; e += 4) {
    uint4 r0 = REC[e], r1 = REC[e + 1], r2 = REC[e + 2], r3 = REC[e + 3];
    uint4 h0 = H4[(size_t)r0.x * 32 + lane];
    uint4 h1 = H4[(size_t)r1.x * 32 + lane];
    uint4 h2 = H4[(size_t)r2.x * 32 + lane];
    uint4 h3 = H4[(size_t)r3.x * 32 + lane];
    EDGE_ACC(h0, r0);
    EDGE_ACC(h1, r1);
    EDGE_ACC(h2, r2);
    EDGE_ACC(h3, r3);
  }
  for (; e < end; e++) {
    uint4 rv = REC[e];
    uint4 hv = H4[(size_t)rv.x * 32 + lane];
    EDGE_ACC(hv, rv);
  }
#undef EDGE_ACC

  float2 d01 = unpack2(dd01), d23 = unpack2(dd23);
  float2 a0 = unpack2(acc0), a1 = unpack2(acc1), a2 = unpack2(acc2), a3 = unpack2(acc3);
  float r0 = 1.f / d01.x, r1 = 1.f / d01.y, r2 = 1.f / d23.x, r3 = 1.f / d23.y;
  float2 bv = ((const float2*)bias)[lane];
  float2 o;
  o.x = (a0.x * r0 + a1.x * r1 + a2.x * r2 + a3.x * r3) * 0.25f + bv.x;
  o.y = (a0.y * r0 + a1.y * r1 + a2.y * r2 + a3.y * r3) * 0.25f + bv.y;
  if (fp16_relu) {
    o.x = fmaxf(o.x, 0.f); o.y = fmaxf(o.y, 0.f);
    ((__half2*)g_xh)[(size_t)w * 32 + lane] = __floats2half2_rn(o.x, o.y);
  } else {
    ((float2*)xout)[(size_t)w * 32 + lane] = o;
  }
}

// ---------------- per-node MLP heads (grid-stride; weights loaded once per block) ----------------
__global__ void __launch_bounds__(256) k_heads(
                        const float* __restrict__ emb,
                        const float* __restrict__ aw1, const float* __restrict__ ab1,
                        const float* __restrict__ aw2, const float* __restrict__ ab2,
                        const float* __restrict__ rw1, const float* __restrict__ rb1,
                        const float* __restrict__ rw2, const float* __restrict__ rb2,
                        const float* __restrict__ cw1, const float* __restrict__ cb1,
                        const float* __restrict__ cw2, const float* __restrict__ cb2,
                        float* __restrict__ anomaly, float* __restrict__ risk,
                        float* __restrict__ resource) {
  __shared__ float s_a1[2048], s_r1[2048], s_c1[2048];
  __shared__ float s_a2[32], s_r2[32], s_c2[160];
  __shared__ float s_ab1[32], s_rb1[32], s_cb1[32];
  __shared__ float s_ab2, s_rb2, s_cb2[5];
  int tid = threadIdx.x;
  for (int t = tid; t < 2048; t += blockDim.x) { s_a1[t] = aw1[t]; s_r1[t] = rw1[t]; s_c1[t] = cw1[t]; }
  for (int t = tid; t < 160; t += blockDim.x) s_c2[t] = cw2[t];
  if (tid < 32) { s_a2[tid] = aw2[tid]; s_r2[tid] = rw2[tid];
                  s_ab1[tid] = ab1[tid]; s_rb1[tid] = rb1[tid]; s_cb1[tid] = cb1[tid]; }
  if (tid == 0) { s_ab2 = ab2[0]; s_rb2 = rb2[0]; }
  if (tid < 5) s_cb2[tid] = cb2[tid];
  __syncthreads();
  int lane = tid & 31;
  int wlocal = tid >> 5;
  int nwarps = (gridDim.x * blockDim.x) >> 5;
  for (int w = blockIdx.x * (blockDim.x >> 5) + wlocal; w < NNODES; w += nwarps) {
    float e0 = emb[(size_t)w * 64 + lane];
    float e1 = emb[(size_t)w * 64 + 32 + lane];
    float ha = s_ab1[lane], hr = s_rb1[lane], hc = s_cb1[lane];
    #pragma unroll
    for (int c = 0; c < 32; c++) {
      float x = __shfl_sync(0xffffffffu, e0, c);
      ha = fmaf(x, s_a1[c * 32 + lane], ha);
      hr = fmaf(x, s_r1[c * 32 + lane], hr);
      hc = fmaf(x, s_c1[c * 32 + lane], hc);
    }
    #pragma unroll
    for (int c = 0; c < 32; c++) {
      float x = __shfl_sync(0xffffffffu, e1, c);
      ha = fmaf(x, s_a1[(c + 32) * 32 + lane], ha);
      hr = fmaf(x, s_r1[(c + 32) * 32 + lane], hr);
      hc = fmaf(x, s_c1[(c + 32) * 32 + lane], hc);
    }
    ha = fmaxf(ha, 0.f); hr = fmaxf(hr, 0.f); hc = fmaxf(hc, 0.f);
    float pa = warp_sum(ha * s_a2[lane]);
    float pr = warp_sum(hr * s_r2[lane]);
    if (lane == 0) {
      anomaly[w] = 1.f / (1.f + __expf(-(pa + s_ab2)));
      risk[w]    = 1.f / (1.f + __expf(-(pr + s_rb2)));
    }
    #pragma unroll
    for (int o = 0; o < 5; o++) {
      float p = warp_sum(hc * s_c2[lane * 5 + o]);
      if (lane == 0) resource[(size_t)w * 5 + o] = p + s_cb2[o];
    }
  }
}

// ---------------- global mean pool + graph MLP ----------------
__global__ void k_pool(const float* __restrict__ emb, const int* __restrict__ batch,
                       const float* __restrict__ gw1, const float* __restrict__ gb1,
                       const float* __restrict__ gw2, const float* __restrict__ gb2,
                       float* __restrict__ glog) {
  __shared__ float part[256];
  __shared__ float pooled[64];
  __shared__ float hidden[32];
  __shared__ int s_lo, s_hi;
  int g = blockIdx.x;
  int tid = threadIdx.x;
  if (tid == 0) {
    int lo = 0, hi = NNODES;
    while (lo < hi) { int mid = (lo + hi) >> 1; if (batch[mid] < g) lo = mid + 1; else hi = mid; }
    int lo2 = lo, hi2 = NNODES;
    while (lo2 < hi2) { int mid = (lo2 + hi2) >> 1; if (batch[mid] <= g) lo2 = mid + 1; else hi2 = mid; }
    s_lo = lo; s_hi = lo2;
  }
  __syncthreads();
  int lo = s_lo, hi = s_hi;
  int c = tid & 63, sub = tid >> 6;
  float acc = 0.f;
  for (int i = lo + sub; i < hi; i += 4) acc += emb[(size_t)i * 64 + c];
  part[tid] = acc;
  __syncthreads();
  if (tid < 64) {
    float cnt = fmaxf((float)(hi - lo), 1.f);
    pooled[tid] = (part[tid] + part[tid + 64] + part[tid + 128] + part[tid + 192]) / cnt;
  }
  __syncthreads();
  if (tid < 32) {
    float h = gb1[tid];
    #pragma unroll
    for (int cc = 0; cc < 64; cc++) h = fmaf(pooled[cc], gw1[cc * 32 + tid], h);
    hidden[tid] = fmaxf(h, 0.f);
  }
  __syncthreads();
  if (tid < 4) {
    float o = gb2[tid];
    #pragma unroll
    for (int j = 0; j < 32; j++) o = fmaf(hidden[j], gw2[j * 4 + tid], o);
    glog[g * 4 + tid] = o;
  }
}

// ---------------- launch ----------------
extern "C" void kernel_launch(void* const* d_in, const int* in_sizes, int n_in,
                              void* d_out, int out_size) {
  const float* x     = (const float*)d_in[0];
  const int*   ei    = (const int*)d_in[1];
  const int*   batch = (const int*)d_in[2];
  const float* W1  = (const float*)d_in[3];
  const float* as1 = (const float*)d_in[4];
  const float* ad1 = (const float*)d_in[5];
  const float* b1  = (const float*)d_in[6];
  const float* W2  = (const float*)d_in[7];
  const float* as2 = (const float*)d_in[8];
  const float* ad2 = (const float*)d_in[9];
  const float* b2  = (const float*)d_in[10];
  const float* W3  = (const float*)d_in[11];
  const float* as3 = (const float*)d_in[12];
  const float* ad3 = (const float*)d_in[13];
  const float* b3  = (const float*)d_in[14];
  const float* aw1 = (const float*)d_in[15];
  const float* ab1 = (const float*)d_in[16];
  const float* aw2 = (const float*)d_in[17];
  const float* ab2 = (const float*)d_in[18];
  const float* rw1 = (const float*)d_in[19];
  const float* rb1 = (const float*)d_in[20];
  const float* rw2 = (const float*)d_in[21];
  const float* rb2 = (const float*)d_in[22];
  const float* cw1 = (const float*)d_in[23];
  const float* cb1 = (const float*)d_in[24];
  const float* cw2 = (const float*)d_in[25];
  const float* cb2 = (const float*)d_in[26];
  const float* gw1 = (const float*)d_in[27];
  const float* gb1 = (const float*)d_in[28];
  const float* gw2 = (const float*)d_in[29];
  const float* gb2 = (const float*)d_in[30];

  float* out      = (float*)d_out;
  float* emb      = out;                               // [N,64]
  float* anomaly  = emb + (size_t)NNODES * 64;         // [N]
  float* risk     = anomaly + NNODES;                  // [N]
  float* resource = risk + NNODES;                     // [N,5]
  float* glog     = resource + (size_t)NNODES * 5;     // [G,4]

  const int SMEM128 = 128 * 136 * 2 + 128 * 72 * 2 + 512;   // 53760
  const int SMEM64  = 128 * 72 * 2 + 64 * 72 * 2 + 512;     // 28160
  cudaFuncSetAttribute(k_gemm_mma<128, true>, cudaFuncAttributeMaxDynamicSharedMemorySize, SMEM128);
  cudaFuncSetAttribute(k_gemm_mma<64, false>, cudaFuncAttributeMaxDynamicSharedMemorySize, SMEM64);

  // One-time side-stream/event/symbol setup (outside graph capture; first call
  // is the eager correctness run). Reused every call -> identical captures.
  static cudaStream_t s2 = nullptr;
  static cudaEvent_t evF, evJ, evF2, evJ2;
  static void* deg_ptr = nullptr;
  if (s2 == nullptr) {
    cudaStreamCreateWithFlags(&s2, cudaStreamNonBlocking);
    cudaEventCreateWithFlags(&evF, cudaEventDisableTiming);
    cudaEventCreateWithFlags(&evJ, cudaEventDisableTiming);
    cudaEventCreateWithFlags(&evF2, cudaEventDisableTiming);
    cudaEventCreateWithFlags(&evJ2, cudaEventDisableTiming);
    cudaGetSymbolAddress(&deg_ptr, g_deg);
  }

  dim3 gemm_grid(4, (NNODES + 127) / 128);
  int warp_blocks = (NNODES * 32 + 255) / 256;
  int pair_blocks = (NETOT / 2 + 255) / 256;

  // Fork: side stream builds CSR prefix while main stream does gemm1 (xcast fused).
  cudaEventRecord(evF, 0);
  cudaStreamWaitEvent(s2, evF, 0);
  cudaMemsetAsync(deg_ptr, 0, NNODES * sizeof(int), s2);
  k_count<<<(NEDGES / 4 + 255) / 256, 256, 0, s2>>>(ei);
  k_scan1<<<NBLK_SCAN, 256, 0, s2>>>();
  k_scan23<<<NBLK_SCAN, 256, 0, s2>>>();
  cudaEventRecord(evJ, s2);

  k_gemm_mma<128, true><<<gemm_grid, 256, SMEM128>>>(x, W1, as1, ad1);

  // Join: fill needs CSR prefix (side) and gemm1 logits (main).
  cudaStreamWaitEvent(0, evJ, 0);
  k_fill_ew1<<<pair_blocks, 256>>>(ei);

  // Layer 1 (aggregate runs alone, full device)
  k_aggregate<<<warp_blocks, 256>>>(b1, nullptr, 1);      // -> g_xh fp16 + relu
  // Layer 2
  k_gemm_mma<64, false><<<gemm_grid, 256, SMEM64>>>(nullptr, W2, as2, ad2);
  k_edgew<<<pair_blocks, 256>>>();
  k_aggregate<<<warp_blocks, 256>>>(b2, nullptr, 1);      // -> g_xh fp16 + relu
  // Layer 3
  k_gemm_mma<64, false><<<gemm_grid, 256, SMEM64>>>(nullptr, W3, as3, ad3);
  k_edgew<<<pair_blocks, 256>>>();
  k_aggregate<<<warp_blocks, 256>>>(b3, emb, 0);          // -> emb fp32, no relu

  // Heads (main) and pooling (side) run concurrently on emb.
  cudaEventRecord(evF2, 0);
  cudaStreamWaitEvent(s2, evF2, 0);
  k_pool<<<NGRAPH, 256, 0, s2>>>(emb, batch, gw1, gb1, gw2, gb2, glog);
  cudaEventRecord(evJ2, s2);
  k_heads<<<HEADS_BLOCKS, 256>>>(emb, aw1, ab1, aw2, ab2,
                                 rw1, rb1, rw2, rb2,
                                 cw1, cb1, cw2, cb2,
                                 anomaly, risk, resource);
  cudaStreamWaitEvent(0, evJ2, 0);
}

// round 14
// speedup vs baseline: 1.2600x; 1.0201x over previous
#include <cuda_runtime.h>
#include <cuda_fp16.h>
#include <math.h>

#define NNODES 50000
#define NEDGES 800000
#define NETOT  (NEDGES + NNODES)
#define NGRAPH 64
#define NBLK_SCAN ((NNODES + 255) / 256)   // 196
#define HEADS_BLOCKS 592
#define GEMM_BLOCKS ((NNODES + 127) / 128) // 391

// ---------------- scratch (device globals; no allocation allowed) ----------------
__device__ __half g_hh[NNODES * 256];    // projected features fp16; lane-interleaved
__device__ __half g_xh[NNODES * 64];     // layer-2/3 input, fp16
__device__ float g_als[NNODES * 4];      // src attention logit per head
__device__ float g_ald[NNODES * 4];      // dst attention logit per head
__device__ int   g_deg[NNODES];
__device__ int   g_rowptr[NNODES + 1];
__device__ int   g_cursor[NNODES];
__device__ int   g_bsum[256];
__device__ uint4 g_erec[NETOT];          // AoS: {src, dst, ew01(h2), ew23(h2)}

// ---------------- helpers ----------------
__device__ __forceinline__ float warp_sum(float v) {
  #pragma unroll
  for (int o = 16; o; o >>= 1) v += __shfl_xor_sync(0xffffffffu, v, o);
  return v;
}
__device__ __forceinline__ float lrelu(float v) { return v > 0.f ? v : 0.2f * v; }

typedef unsigned long long ull;
__device__ __forceinline__ ull pack2(float x, float y) {
  ull r; asm("mov.b64 %0,{%1,%2};" : "=l"(r) : "f"(x), "f"(y)); return r;
}
__device__ __forceinline__ void ffma2(ull& d, ull a, ull b) {
  asm("fma.rn.f32x2 %0,%1,%2,%0;" : "+l"(d) : "l"(a), "l"(b));
}
__device__ __forceinline__ void fadd2(ull& d, ull a) {
  asm("add.rn.f32x2 %0,%0,%1;" : "+l"(d) : "l"(a));
}
__device__ __forceinline__ float2 unpack2(ull v) {
  float2 f; asm("mov.b64 {%0,%1},%2;" : "=f"(f.x), "=f"(f.y) : "l"(v)); return f;
}

// ---------------- CSR build ----------------
__global__ void k_count(const int* __restrict__ ei) {
  int t = blockIdx.x * blockDim.x + threadIdx.x;
  if (t >= NEDGES / 4) return;
  int4 d4 = ((const int4*)(ei + NEDGES))[t];
  atomicAdd(&g_deg[d4.x], 1);
  atomicAdd(&g_deg[d4.y], 1);
  atomicAdd(&g_deg[d4.z], 1);
  atomicAdd(&g_deg[d4.w], 1);
}

__global__ void k_scan1() {
  __shared__ int tmp[256];
  int tid = threadIdx.x;
  int i = blockIdx.x * 256 + tid;
  int v = (i < NNODES) ? g_deg[i] + 1 : 0;   // +1 = self-loop
  tmp[tid] = v;
  __syncthreads();
  #pragma unroll
  for (int d = 1; d < 256; d <<= 1) {
    int t = (tid >= d) ? tmp[tid - d] : 0;
    __syncthreads();
    tmp[tid] += t;
    __syncthreads();
  }
  if (i < NNODES) g_rowptr[i] = tmp[tid] - v;   // exclusive within block
  if (tid == 255) g_bsum[blockIdx.x] = tmp[255];
}

__global__ void k_scan23() {
  __shared__ int red[256];
  int tid = threadIdx.x;
  int bid = blockIdx.x;
  int v = (tid < bid && tid < NBLK_SCAN) ? g_bsum[tid] : 0;
  red[tid] = v;
  __syncthreads();
  #pragma unroll
  for (int o = 128; o; o >>= 1) {
    if (tid < o) red[tid] += red[tid + o];
    __syncthreads();
  }
  int off = red[0];
  int i = bid * 256 + tid;
  if (i < NNODES) {
    int r = g_rowptr[i] + off;
    g_rowptr[i] = r;
    g_cursor[i] = r;
  }
  if (i == 0) g_rowptr[NNODES] = NETOT;
}

// fill CSR record AND layer-1 edge weights; 2 edges per thread
__device__ __forceinline__ void fill_one(int s, int d) {
  int pos = atomicAdd(&g_cursor[d], 1);
  float4 as = ((const float4*)g_als)[s];
  float4 ad = ((const float4*)g_ald)[d];
  __half2 e01 = __floats2half2_rn(__expf(lrelu(as.x + ad.x)), __expf(lrelu(as.y + ad.y)));
  __half2 e23 = __floats2half2_rn(__expf(lrelu(as.z + ad.z)), __expf(lrelu(as.w + ad.w)));
  uint4 rec;
  rec.x = (unsigned)s;
  rec.y = (unsigned)d;
  rec.z = *reinterpret_cast<unsigned*>(&e01);
  rec.w = *reinterpret_cast<unsigned*>(&e23);
  g_erec[pos] = rec;
}

__global__ void k_fill_ew1(const int* __restrict__ ei) {
  int j = blockIdx.x * blockDim.x + threadIdx.x;
  if (j >= NETOT / 2) return;
  int e0 = 2 * j;
  if (e0 < NEDGES) {
    int2 ss = *(const int2*)&ei[e0];
    int2 dd = *(const int2*)&ei[NEDGES + e0];
    fill_one(ss.x, dd.x);
    fill_one(ss.y, dd.y);
  } else {
    int n0 = e0 - NEDGES;
    fill_one(n0, n0);
    fill_one(n0 + 1, n0 + 1);
  }
}

// ---------------- edge-parallel softmax weights (layers 2, 3) ----------------
__device__ __forceinline__ void edgew_one(int e) {
  int2 sd = *reinterpret_cast<const int2*>(&g_erec[e]);
  float4 as = ((const float4*)g_als)[sd.x];
  float4 ad = ((const float4*)g_ald)[sd.y];
  __half2 e01 = __floats2half2_rn(__expf(lrelu(as.x + ad.x)), __expf(lrelu(as.y + ad.y)));
  __half2 e23 = __floats2half2_rn(__expf(lrelu(as.z + ad.z)), __expf(lrelu(as.w + ad.w)));
  uint2 wv;
  wv.x = *reinterpret_cast<unsigned*>(&e01);
  wv.y = *reinterpret_cast<unsigned*>(&e23);
  *reinterpret_cast<uint2*>(reinterpret_cast<char*>(&g_erec[e]) + 8) = wv;
}

__global__ void k_edgew() {
  int j = blockIdx.x * blockDim.x + threadIdx.x;
  if (j >= NETOT / 2) return;
  edgew_one(2 * j);
  edgew_one(2 * j + 1);
}

// ---------------- tensor-core GEMM (128x256 tile, all heads) + logit epilogue ----------------
__device__ __forceinline__ void ldsm4(unsigned& r0, unsigned& r1, unsigned& r2, unsigned& r3,
                                      unsigned addr) {
  asm volatile("ldmatrix.sync.aligned.m8n8.x4.shared.b16 {%0,%1,%2,%3}, [%4];"
               : "=r"(r0), "=r"(r1), "=r"(r2), "=r"(r3) : "r"(addr));
}
__device__ __forceinline__ void ldsm2t(unsigned& r0, unsigned& r1, unsigned addr) {
  asm volatile("ldmatrix.sync.aligned.m8n8.x2.trans.shared.b16 {%0,%1}, [%2];"
               : "=r"(r0), "=r"(r1) : "r"(addr));
}
__device__ __forceinline__ void mma16816(float* c, const unsigned* a, const unsigned* b) {
  asm volatile("mma.sync.aligned.m16n8k16.row.col.f32.f16.f16.f32 "
               "{%0,%1,%2,%3},{%4,%5,%6,%7},{%8,%9},{%0,%1,%2,%3};"
               : "+f"(c[0]), "+f"(c[1]), "+f"(c[2]), "+f"(c[3])
               : "r"(a[0]), "r"(a[1]), "r"(a[2]), "r"(a[3]), "r"(b[0]), "r"(b[1]));
}

// Block: 128 rows x 256 cols (all 4 heads). 512 threads, warp grid 4m x 4n
// (warp_n == head). A loaded once. Epilogue stages to smem in the aggregate's
// interleaved layout, then writes full coalesced 512B rows.
// CVT=true: A loaded from fp32 Xf (layer 1, xcast fused); else fp16 g_xh.
template<int K, bool CVT>
__global__ void __launch_bounds__(512, 1) k_gemm_mma(
    const float* __restrict__ Xf, const float* __restrict__ W,
    const float* __restrict__ a_s, const float* __restrict__ a_d) {
  constexpr int APAD = K + 8;
  constexpr int A_BYTES = 128 * APAD * 2;
  constexpr int B_BYTES = K * 264 * 2;
  constexpr int ST_BYTES = 128 * 264 * 2;           // staging, overlays A+B
  constexpr int S_OFF = (A_BYTES + B_BYTES > ST_BYTES) ? (A_BYTES + B_BYTES) : ST_BYTES;
  extern __shared__ __align__(16) char dyn[];
  __half* As = (__half*)dyn;
  __half* Bs = (__half*)(dyn + A_BYTES);
  __half* St = (__half*)dyn;                        // staging overlay
  float* s_as = (float*)(dyn + S_OFF);
  float* s_ad = s_as + 256;

  int tid = threadIdx.x;
  int lane = tid & 31, wid = tid >> 5;
  int warp_m = wid >> 2, hd = wid & 3;              // warp_n == head
  int row0 = blockIdx.x * 128;

  if (tid < 256) { s_as[tid] = a_s[tid]; s_ad[tid] = a_d[tid]; }

  // load A [128 x K]
  if (CVT) {
    constexpr int A_IT = 128 * (K / 4) / 512;
    #pragma unroll
    for (int it = 0; it < A_IT; it++) {
      int idx = tid + it * 512;
      int r = idx / (K / 4), c4 = idx % (K / 4);
      float4 v = make_float4(0.f, 0.f, 0.f, 0.f);
      if (row0 + r < NNODES)
        v = *(const float4*)&Xf[(size_t)(row0 + r) * K + c4 * 4];
      __half2 h01 = __floats2half2_rn(v.x, v.y);
      __half2 h23 = __floats2half2_rn(v.z, v.w);
      uint2 st;
      st.x = *reinterpret_cast<unsigned*>(&h01);
      st.y = *reinterpret_cast<unsigned*>(&h23);
      *(uint2*)&As[r * APAD + c4 * 4] = st;
    }
  } else {
    constexpr int A_IT = 128 * (K / 8) / 512;
    #pragma unroll
    for (int it = 0; it < A_IT; it++) {
      int idx = tid + it * 512;
      int r = idx / (K / 8), c8 = idx % (K / 8);
      uint4 v = make_uint4(0, 0, 0, 0);
      if (row0 + r < NNODES)
        v = *(const uint4*)&g_xh[(size_t)(row0 + r) * K + c8 * 8];
      *(uint4*)&As[r * APAD + c8 * 8] = v;
    }
  }
  // load + convert B [K x 256]
  constexpr int B_IT = K * 64 / 512;
  #pragma unroll
  for (int it = 0; it < B_IT; it++) {
    int idx = tid + it * 512;
    int k = idx >> 6, c4 = idx & 63;
    float4 v = *(const float4*)&W[(size_t)k * 256 + c4 * 4];
    __half2* o = (__half2*)&Bs[k * 264 + c4 * 4];
    o[0] = __floats2half2_rn(v.x, v.y);
    o[1] = __floats2half2_rn(v.z, v.w);
  }
  __syncthreads();

  unsigned As_u = (unsigned)__cvta_generic_to_shared(As);
  unsigned Bs_u = (unsigned)__cvta_generic_to_shared(Bs);
  unsigned a_base = As_u + ((warp_m * 32 + (lane & 15)) * APAD + (lane >> 4) * 8) * 2;
  unsigned b_base = Bs_u + ((lane & 15) * 264 + hd * 64) * 2;

  float acc[2][8][4];
  #pragma unroll
  for (int mt = 0; mt < 2; mt++)
    #pragma unroll
    for (int nt = 0; nt < 8; nt++)
      #pragma unroll
      for (int q = 0; q < 4; q++) acc[mt][nt][q] = 0.f;

  #pragma unroll
  for (int ks = 0; ks < K / 16; ks++) {
    unsigned a[2][4], b[8][2];
    #pragma unroll
    for (int mt = 0; mt < 2; mt++)
      ldsm4(a[mt][0], a[mt][1], a[mt][2], a[mt][3],
            a_base + (mt * 16 * APAD + ks * 16) * 2);
    #pragma unroll
    for (int nt = 0; nt < 8; nt++)
      ldsm2t(b[nt][0], b[nt][1], b_base + (ks * 16 * 264 + nt * 8) * 2);
    #pragma unroll
    for (int mt = 0; mt < 2; mt++)
      #pragma unroll
      for (int nt = 0; nt < 8; nt++)
        mma16816(acc[mt][nt], a[mt], b[nt]);
  }
  __syncthreads();   // staging overlays As/Bs

  // epilogue: logits (warp covers full head) + staged interleaved store
  int quad = lane >> 2, qid = lane & 3;
  #pragma unroll
  for (int mt = 0; mt < 2; mt++) {
    #pragma unroll
    for (int rh = 0; rh < 2; rh++) {
      int lr = warp_m * 32 + mt * 16 + rh * 8 + quad;
      int row = row0 + lr;
      float ss = 0.f, sd = 0.f;
      #pragma unroll
      for (int nt = 0; nt < 8; nt++) {
        float v0 = acc[mt][nt][rh * 2 + 0];
        float v1 = acc[mt][nt][rh * 2 + 1];
        int c = nt * 8 + qid * 2;                   // in-head channel (even)
        ss = fmaf(v0, s_as[hd * 64 + c], fmaf(v1, s_as[hd * 64 + c + 1], ss));
        sd = fmaf(v0, s_ad[hd * 64 + c], fmaf(v1, s_ad[hd * 64 + c + 1], sd));
        // interleaved layout: halves idx = 8*(c/2) + 2*hd + parity
        *(__half2*)&St[lr * 264 + 32 * nt + 8 * qid + 2 * hd] = __floats2half2_rn(v0, v1);
      }
      ss += __shfl_xor_sync(0xffffffffu, ss, 1);
      ss += __shfl_xor_sync(0xffffffffu, ss, 2);
      sd += __shfl_xor_sync(0xffffffffu, sd, 1);
      sd += __shfl_xor_sync(0xffffffffu, sd, 2);
      if (qid == 0 && row < NNODES) {
        g_als[row * 4 + hd] = ss;
        g_ald[row * 4 + hd] = sd;
      }
    }
  }
  __syncthreads();

  // coalesced copy-out: 128 rows x 32 uint4
  #pragma unroll
  for (int it = 0; it < 8; it++) {
    int idx = tid + it * 512;
    int r = idx >> 5, q = idx & 31;
    if (row0 + r < NNODES)
      ((uint4*)&g_hh[(size_t)(row0 + r) * 256])[q] = *(const uint4*)&St[r * 264 + q * 8];
  }
}

// ---------------- GAT aggregate (one warp per node, full range, runs alone) ----------------
__global__ void k_aggregate(const float* __restrict__ bias, float* __restrict__ xout,
                            int fp16_relu) {
  int w = (blockIdx.x * blockDim.x + threadIdx.x) >> 5;
  int lane = threadIdx.x & 31;
  if (w >= NNODES) return;
  int beg = g_rowptr[w], end = g_rowptr[w + 1];
  const uint4* __restrict__ H4 = (const uint4*)g_hh;     // 32 uint4 per row
  const uint4* __restrict__ REC = (const uint4*)g_erec;

  ull acc0 = 0, acc1 = 0, acc2 = 0, acc3 = 0;
  ull dd01 = 0, dd23 = 0;

#define EDGE_ACC(hv, rec)                                                 \
  do {                                                                    \
    float2 w01 = __half22float2(*reinterpret_cast<const __half2*>(&(rec).z)); \
    float2 w23 = __half22float2(*reinterpret_cast<const __half2*>(&(rec).w)); \
    fadd2(dd01, pack2(w01.x, w01.y));                                     \
    fadd2(dd23, pack2(w23.x, w23.y));                                     \
    float2 f0 = __half22float2(*(__half2*)&(hv).x);                       \
    float2 f1 = __half22float2(*(__half2*)&(hv).y);                       \
    float2 f2 = __half22float2(*(__half2*)&(hv).z);                       \
    float2 f3 = __half22float2(*(__half2*)&(hv).w);                       \
    ffma2(acc0, pack2(f0.x, f0.y), pack2(w01.x, w01.x));                  \
    ffma2(acc1, pack2(f1.x, f1.y), pack2(w01.y, w01.y));                  \
    ffma2(acc2, pack2(f2.x, f2.y), pack2(w23.x, w23.x));                  \
    ffma2(acc3, pack2(f3.x, f3.y), pack2(w23.y, w23.y));                  \
  } while (0)

  int e = beg;
  for (; e + 4 <= end; e += 4) {
    uint4 r0 = REC[e], r1 = REC[e + 1], r2 = REC[e + 2], r3 = REC[e + 3];
    uint4 h0 = H4[(size_t)r0.x * 32 + lane];
    uint4 h1 = H4[(size_t)r1.x * 32 + lane];
    uint4 h2 = H4[(size_t)r2.x * 32 + lane];
    uint4 h3 = H4[(size_t)r3.x * 32 + lane];
    EDGE_ACC(h0, r0);
    EDGE_ACC(h1, r1);
    EDGE_ACC(h2, r2);
    EDGE_ACC(h3, r3);
  }
  for (; e < end; e++) {
    uint4 rv = REC[e];
    uint4 hv = H4[(size_t)rv.x * 32 + lane];
    EDGE_ACC(hv, rv);
  }
#undef EDGE_ACC

  float2 d01 = unpack2(dd01), d23 = unpack2(dd23);
  float2 a0 = unpack2(acc0), a1 = unpack2(acc1), a2 = unpack2(acc2), a3 = unpack2(acc3);
  float r0 = 1.f / d01.x, r1 = 1.f / d01.y, r2 = 1.f / d23.x, r3 = 1.f / d23.y;
  float2 bv = ((const float2*)bias)[lane];
  float2 o;
  o.x = (a0.x * r0 + a1.x * r1 + a2.x * r2 + a3.x * r3) * 0.25f + bv.x;
  o.y = (a0.y * r0 + a1.y * r1 + a2.y * r2 + a3.y * r3) * 0.25f + bv.y;
  if (fp16_relu) {
    o.x = fmaxf(o.x, 0.f); o.y = fmaxf(o.y, 0.f);
    ((__half2*)g_xh)[(size_t)w * 32 + lane] = __floats2half2_rn(o.x, o.y);
  } else {
    ((float2*)xout)[(size_t)w * 32 + lane] = o;
  }
}

// ---------------- per-node MLP heads (grid-stride; weights loaded once per block) ----------------
__global__ void __launch_bounds__(256) k_heads(
                        const float* __restrict__ emb,
                        const float* __restrict__ aw1, const float* __restrict__ ab1,
                        const float* __restrict__ aw2, const float* __restrict__ ab2,
                        const float* __restrict__ rw1, const float* __restrict__ rb1,
                        const float* __restrict__ rw2, const float* __restrict__ rb2,
                        const float* __restrict__ cw1, const float* __restrict__ cb1,
                        const float* __restrict__ cw2, const float* __restrict__ cb2,
                        float* __restrict__ anomaly, float* __restrict__ risk,
                        float* __restrict__ resource) {
  __shared__ float s_a1[2048], s_r1[2048], s_c1[2048];
  __shared__ float s_a2[32], s_r2[32], s_c2[160];
  __shared__ float s_ab1[32], s_rb1[32], s_cb1[32];
  __shared__ float s_ab2, s_rb2, s_cb2[5];
  int tid = threadIdx.x;
  for (int t = tid; t < 2048; t += blockDim.x) { s_a1[t] = aw1[t]; s_r1[t] = rw1[t]; s_c1[t] = cw1[t]; }
  for (int t = tid; t < 160; t += blockDim.x) s_c2[t] = cw2[t];
  if (tid < 32) { s_a2[tid] = aw2[tid]; s_r2[tid] = rw2[tid];
                  s_ab1[tid] = ab1[tid]; s_rb1[tid] = rb1[tid]; s_cb1[tid] = cb1[tid]; }
  if (tid == 0) { s_ab2 = ab2[0]; s_rb2 = rb2[0]; }
  if (tid < 5) s_cb2[tid] = cb2[tid];
  __syncthreads();
  int lane = tid & 31;
  int wlocal = tid >> 5;
  int nwarps = (gridDim.x * blockDim.x) >> 5;
  for (int w = blockIdx.x * (blockDim.x >> 5) + wlocal; w < NNODES; w += nwarps) {
    float e0 = emb[(size_t)w * 64 + lane];
    float e1 = emb[(size_t)w * 64 + 32 + lane];
    float ha = s_ab1[lane], hr = s_rb1[lane], hc = s_cb1[lane];
    #pragma unroll
    for (int c = 0; c < 32; c++) {
      float x = __shfl_sync(0xffffffffu, e0, c);
      ha = fmaf(x, s_a1[c * 32 + lane], ha);
      hr = fmaf(x, s_r1[c * 32 + lane], hr);
      hc = fmaf(x, s_c1[c * 32 + lane], hc);
    }
    #pragma unroll
    for (int c = 0; c < 32; c++) {
      float x = __shfl_sync(0xffffffffu, e1, c);
      ha = fmaf(x, s_a1[(c + 32) * 32 + lane], ha);
      hr = fmaf(x, s_r1[(c + 32) * 32 + lane], hr);
      hc = fmaf(x, s_c1[(c + 32) * 32 + lane], hc);
    }
    ha = fmaxf(ha, 0.f); hr = fmaxf(hr, 0.f); hc = fmaxf(hc, 0.f);
    float pa = warp_sum(ha * s_a2[lane]);
    float pr = warp_sum(hr * s_r2[lane]);
    if (lane == 0) {
      anomaly[w] = 1.f / (1.f + __expf(-(pa + s_ab2)));
      risk[w]    = 1.f / (1.f + __expf(-(pr + s_rb2)));
    }
    #pragma unroll
    for (int o = 0; o < 5; o++) {
      float p = warp_sum(hc * s_c2[lane * 5 + o]);
      if (lane == 0) resource[(size_t)w * 5 + o] = p + s_cb2[o];
    }
  }
}

// ---------------- global mean pool + graph MLP ----------------
__global__ void k_pool(const float* __restrict__ emb, const int* __restrict__ batch,
                       const float* __restrict__ gw1, const float* __restrict__ gb1,
                       const float* __restrict__ gw2, const float* __restrict__ gb2,
                       float* __restrict__ glog) {
  __shared__ float part[256];
  __shared__ float pooled[64];
  __shared__ float hidden[32];
  __shared__ int s_lo, s_hi;
  int g = blockIdx.x;
  int tid = threadIdx.x;
  if (tid == 0) {
    int lo = 0, hi = NNODES;
    while (lo < hi) { int mid = (lo + hi) >> 1; if (batch[mid] < g) lo = mid + 1; else hi = mid; }
    int lo2 = lo, hi2 = NNODES;
    while (lo2 < hi2) { int mid = (lo2 + hi2) >> 1; if (batch[mid] <= g) lo2 = mid + 1; else hi2 = mid; }
    s_lo = lo; s_hi = lo2;
  }
  __syncthreads();
  int lo = s_lo, hi = s_hi;
  int c = tid & 63, sub = tid >> 6;
  float acc = 0.f;
  for (int i = lo + sub; i < hi; i += 4) acc += emb[(size_t)i * 64 + c];
  part[tid] = acc;
  __syncthreads();
  if (tid < 64) {
    float cnt = fmaxf((float)(hi - lo), 1.f);
    pooled[tid] = (part[tid] + part[tid + 64] + part[tid + 128] + part[tid + 192]) / cnt;
  }
  __syncthreads();
  if (tid < 32) {
    float h = gb1[tid];
    #pragma unroll
    for (int cc = 0; cc < 64; cc++) h = fmaf(pooled[cc], gw1[cc * 32 + tid], h);
    hidden[tid] = fmaxf(h, 0.f);
  }
  __syncthreads();
  if (tid < 4) {
    float o = gb2[tid];
    #pragma unroll
    for (int j = 0; j < 32; j++) o = fmaf(hidden[j], gw2[j * 4 + tid], o);
    glog[g * 4 + tid] = o;
  }
}

// ---------------- launch ----------------
extern "C" void kernel_launch(void* const* d_in, const int* in_sizes, int n_in,
                              void* d_out, int out_size) {
  const float* x     = (const float*)d_in[0];
  const int*   ei    = (const int*)d_in[1];
  const int*   batch = (const int*)d_in[2];
  const float* W1  = (const float*)d_in[3];
  const float* as1 = (const float*)d_in[4];
  const float* ad1 = (const float*)d_in[5];
  const float* b1  = (const float*)d_in[6];
  const float* W2  = (const float*)d_in[7];
  const float* as2 = (const float*)d_in[8];
  const float* ad2 = (const float*)d_in[9];
  const float* b2  = (const float*)d_in[10];
  const float* W3  = (const float*)d_in[11];
  const float* as3 = (const float*)d_in[12];
  const float* ad3 = (const float*)d_in[13];
  const float* b3  = (const float*)d_in[14];
  const float* aw1 = (const float*)d_in[15];
  const float* ab1 = (const float*)d_in[16];
  const float* aw2 = (const float*)d_in[17];
  const float* ab2 = (const float*)d_in[18];
  const float* rw1 = (const float*)d_in[19];
  const float* rb1 = (const float*)d_in[20];
  const float* rw2 = (const float*)d_in[21];
  const float* rb2 = (const float*)d_in[22];
  const float* cw1 = (const float*)d_in[23];
  const float* cb1 = (const float*)d_in[24];
  const float* cw2 = (const float*)d_in[25];
  const float* cb2 = (const float*)d_in[26];
  const float* gw1 = (const float*)d_in[27];
  const float* gb1 = (const float*)d_in[28];
  const float* gw2 = (const float*)d_in[29];
  const float* gb2 = (const float*)d_in[30];

  float* out      = (float*)d_out;
  float* emb      = out;                               // [N,64]
  float* anomaly  = emb + (size_t)NNODES * 64;         // [N]
  float* risk     = anomaly + NNODES;                  // [N]
  float* resource = risk + NNODES;                     // [N,5]
  float* glog     = resource + (size_t)NNODES * 5;     // [G,4]

  const int SMEM128 = 128 * 136 * 2 + 128 * 264 * 2 + 2048;  // 104448
  const int SMEM64  = 128 * 264 * 2 + 2048;                  // 69632 (staging > A+B)
  cudaFuncSetAttribute(k_gemm_mma<128, true>, cudaFuncAttributeMaxDynamicSharedMemorySize, SMEM128);
  cudaFuncSetAttribute(k_gemm_mma<64, false>, cudaFuncAttributeMaxDynamicSharedMemorySize, SMEM64);

  static cudaStream_t s2 = nullptr;
  static cudaEvent_t evF, evJ, evF2, evJ2;
  static void* deg_ptr = nullptr;
  if (s2 == nullptr) {
    cudaStreamCreateWithFlags(&s2, cudaStreamNonBlocking);
    cudaEventCreateWithFlags(&evF, cudaEventDisableTiming);
    cudaEventCreateWithFlags(&evJ, cudaEventDisableTiming);
    cudaEventCreateWithFlags(&evF2, cudaEventDisableTiming);
    cudaEventCreateWithFlags(&evJ2, cudaEventDisableTiming);
    cudaGetSymbolAddress(&deg_ptr, g_deg);
  }

  int warp_blocks = (NNODES * 32 + 255) / 256;
  int pair_blocks = (NETOT / 2 + 255) / 256;

  // Fork: side stream builds CSR prefix while main stream does gemm1 (xcast fused).
  cudaEventRecord(evF, 0);
  cudaStreamWaitEvent(s2, evF, 0);
  cudaMemsetAsync(deg_ptr, 0, NNODES * sizeof(int), s2);
  k_count<<<(NEDGES / 4 + 255) / 256, 256, 0, s2>>>(ei);
  k_scan1<<<NBLK_SCAN, 256, 0, s2>>>();
  k_scan23<<<NBLK_SCAN, 256, 0, s2>>>();
  cudaEventRecord(evJ, s2);

  k_gemm_mma<128, true><<<GEMM_BLOCKS, 512, SMEM128>>>(x, W1, as1, ad1);

  // Join: fill needs CSR prefix (side) and gemm1 logits (main).
  cudaStreamWaitEvent(0, evJ, 0);
  k_fill_ew1<<<pair_blocks, 256>>>(ei);

  // Layer 1 (aggregate runs alone, full device)
  k_aggregate<<<warp_blocks, 256>>>(b1, nullptr, 1);      // -> g_xh fp16 + relu
  // Layer 2
  k_gemm_mma<64, false><<<GEMM_BLOCKS, 512, SMEM64>>>(nullptr, W2, as2, ad2);
  k_edgew<<<pair_blocks, 256>>>();
  k_aggregate<<<warp_blocks, 256>>>(b2, nullptr, 1);      // -> g_xh fp16 + relu
  // Layer 3
  k_gemm_mma<64, false><<<GEMM_BLOCKS, 512, SMEM64>>>(nullptr, W3, as3, ad3);
  k_edgew<<<pair_blocks, 256>>>();
  k_aggregate<<<warp_blocks, 256>>>(b3, emb, 0);          // -> emb fp32, no relu

  // Heads (main) and pooling (side) run concurrently on emb.
  cudaEventRecord(evF2, 0);
  cudaStreamWaitEvent(s2, evF2, 0);
  k_pool<<<NGRAPH, 256, 0, s2>>>(emb, batch, gw1, gb1, gw2, gb2, glog);
  cudaEventRecord(evJ2, s2);
  k_heads<<<HEADS_BLOCKS, 256>>>(emb, aw1, ab1, aw2, ab2,
                                 rw1, rb1, rw2, rb2,
                                 cw1, cb1, cw2, cb2,
                                 anomaly, risk, resource);
  cudaStreamWaitEvent(0, evJ2, 0);
}